// round 12
// baseline (speedup 1.0000x reference)
#include <cuda_runtime.h>
#include <cstdint>

#define N_ 2
#define C_ 64
#define D_ 8
#define H_ 56
#define W_ 56
#define G_ 8
#define K_ 27
#define CO_OFF 648
#define P_ (D_*H_*W_)          // 25088
#define DP_ (D_+2)
#define HP_ (H_+2)
#define WP_ (W_+2)
#define PPAD_ (DP_*HP_*WP_)    // 33640
#define HPWP_ (HP_*WP_)

#define PREP_W0 (11*64*64*32)  // 1441792
#define PREP_W1 (216*64*8)     // 110592
#define PREP_W2 (64*64*32)     // 131072
#define PREP_TOT (PREP_W0 + PREP_W1 + PREP_W2)

// ---------------- scratch (no allocation allowed) ----------------
__device__ float g_xpad[N_*C_*PPAD_];    // padded input for offset conv
__device__ float g_y2pad[N_*C_*PPAD_];   // padded bn1+relu output for conv2
__device__ float g_off[N_*CO_OFF*P_];    // offset tensor (130 MB)
__device__ float4 g_xt[N_*G_*P_*2];      // x transposed [n][g][p][8ch] (12.8 MB)
__device__ float g_vals[N_*G_*K_*8*P_];  // sampled values (347 MB)
__device__ float g_y1[N_*C_*P_];         // deform conv output
__device__ float g_y3[N_*C_*P_];         // conv2 output
__device__ float g_stats[4*C_];          // mean1, istd1, mean2, istd2
__device__ float g_wofft[PREP_W0];       // tf32 w_off [cot][ci][co][j32]
__device__ float g_w1H[PREP_W1];         // w1 tf32 [t][o][cl'] (pair-permuted)
__device__ float g_w2H[PREP_W2];         // w2 tf32 [ci][co][j32]

// ---------------- helpers ----------------
__device__ __forceinline__ uint32_t f2tf32(float x) {
    uint32_t r;
    asm("cvt.rna.tf32.f32 %0, %1;" : "=r"(r) : "f"(x));
    return r;
}

__device__ __forceinline__ void mma_tf32(float c[4], const uint32_t a[4],
                                         uint32_t b0, uint32_t b1) {
    asm volatile(
        "mma.sync.aligned.m16n8k8.row.col.f32.tf32.tf32.f32 "
        "{%0,%1,%2,%3}, {%4,%5,%6,%7}, {%8,%9}, {%0,%1,%2,%3};"
        : "+f"(c[0]), "+f"(c[1]), "+f"(c[2]), "+f"(c[3])
        : "r"(a[0]), "r"(a[1]), "r"(a[2]), "r"(a[3]), "r"(b0), "r"(b1));
}

// ---------------- kernel P: weight prep (tf32, GEMM layouts) ----------------
__global__ void prep_kernel(const float* __restrict__ w_off,
                            const float* __restrict__ w1,
                            const float* __restrict__ w2) {
    int idx = blockIdx.x * 256 + threadIdx.x;
    if (idx < PREP_W0) {
        int j = idx & 31, co = (idx >> 5) & 63, ci = (idx >> 11) & 63, cot = idx >> 17;
        int cog = cot * 64 + co;
        float v = (j < 27 && cog < CO_OFF) ? w_off[(size_t)cog * 1728 + ci * 27 + j] : 0.f;
        g_wofft[idx] = __uint_as_float(f2tf32(v));
    } else if (idx < PREP_W0 + PREP_W1) {
        int r = idx - PREP_W0;
        int clp = r & 7, o = (r >> 3) & 63, t = r >> 9;
        int cl = (clp >> 1) + (clp & 1) * 4;
        int g = t / 27, k = t - g * 27;
        float v = w1[(o * C_ + g * 8 + cl) * K_ + k];
        g_w1H[r] = __uint_as_float(f2tf32(v));
    } else if (idx < PREP_TOT) {
        int r = idx - PREP_W0 - PREP_W1;
        int j = r & 31, co = (r >> 5) & 63, ci = r >> 11;
        float v = (j < 27) ? w2[(co * C_ + ci) * 1728 / 64 + j] : 0.f; // placeholder (fixed below)
        // NOTE: correct indexing below
        v = (j < 27) ? w2[(co * C_ + ci) * 27 + j] : 0.f;
        g_w2H[r] = __uint_as_float(f2tf32(v));
    }
}

// ---------------- kernel T: transpose x -> [n][g][p][8ch] ----------------
__global__ void transpose_kernel(const float* __restrict__ x) {
    int idx = blockIdx.x * 256 + threadIdx.x;   // n*g*p
    if (idx >= N_*G_*P_) return;
    int p = idx % P_;
    int g = (idx / P_) % G_;
    int n = idx / (P_ * G_);
    const float* xs = x + ((size_t)(n * C_ + g * 8)) * P_ + p;
    float4 a, b;
    a.x = xs[0];            a.y = xs[(size_t)P_];
    a.z = xs[2*(size_t)P_]; a.w = xs[3*(size_t)P_];
    b.x = xs[4*(size_t)P_]; b.y = xs[5*(size_t)P_];
    b.z = xs[6*(size_t)P_]; b.w = xs[7*(size_t)P_];
    g_xt[(size_t)idx * 2]     = a;
    g_xt[(size_t)idx * 2 + 1] = b;
}

// ---------------- kernel 0: build padded x, zero pad edges of y2pad ----------------
__global__ void padinit_kernel(const float* __restrict__ x) {
    int idx = blockIdx.x * 256 + threadIdx.x;
    if (idx >= N_*C_*PPAD_) return;
    int wp = idx % WP_;
    int hp = (idx / WP_) % HP_;
    int dp = (idx / (WP_*HP_)) % DP_;
    int nc = idx / PPAD_;
    bool interior = (dp >= 1 && dp <= D_ && hp >= 1 && hp <= H_ && wp >= 1 && wp <= W_);
    float v = 0.f;
    if (interior)
        v = x[nc * P_ + (dp-1) * (H_*W_) + (hp-1) * W_ + (wp-1)];
    g_xpad[idx] = v;
    if (!interior) g_y2pad[idx] = 0.f;
}

// ---------------- kernel 1: offset conv, tf32 MMA, 3 blocks/SM, tail-predicated ----
// BM=64 co x BN=224 positions. 256 thr, warps 2M x 4N. grid: (224, 11)
__global__ __launch_bounds__(256, 3) void offconv_mma_kernel(const float* __restrict__ b_off) {
    __shared__ float Ws[64*36];     // weights [co][32k], stride 36
    __shared__ float slab[1044];    // xpad slab [kd 3][hh 6][ww 58] (tf32)
    __shared__ int   lut[32];       // tap -> slab base offset

    int bx = blockIdx.x;
    int hq = bx % 14;
    int h  = hq * 4;
    int d  = (bx / 14) % D_;
    int n  = bx / (14 * D_);
    int cot = blockIdx.y;

    int tid  = threadIdx.x;
    int lane = tid & 31, warp = tid >> 5;
    int gid  = lane >> 2, tg = lane & 3;
    int mw   = warp >> 2, nw = warp & 3;

    // tail-tile liveness (tile cot=10 covers co 640..703, only 640..647 real)
    bool mt_live0 = (cot * 64 + mw * 32)      < CO_OFF;
    bool mt_live1 = (cot * 64 + mw * 32 + 16) < CO_OFF;
    bool any_live = mt_live0 || mt_live1;

    if (tid < 32) {
        int j = tid, base = 0;
        if (j < 27) {
            int kd = j / 9, kh = (j / 3) % 3, kw = j % 3;
            base = kd * 348 + kh * 58 + kw;   // 348 = 6*58
        }
        lut[j] = base;
    }

    float c[2][7][4];
#pragma unroll
    for (int mt = 0; mt < 2; mt++)
#pragma unroll
        for (int nt = 0; nt < 7; nt++)
#pragma unroll
            for (int i = 0; i < 4; i++) c[mt][nt][i] = 0.f;

    const float* xp = g_xpad + n * (C_*PPAD_) + d * HPWP_ + h * WP_;

    for (int ci = 0; ci < C_; ci++) {
        __syncthreads();
        // stage weights: 512 float4 (2 per thread)
        const float4* w4 = (const float4*)(g_wofft + (((size_t)cot * 64 + ci) << 11));
#pragma unroll
        for (int i = tid; i < 512; i += 256) {
            float4 v = w4[i];
            int co = i >> 3, j4 = (i & 7) * 4;
            *(float4*)&Ws[co * 36 + j4] = v;
        }
        // stage slab: 522 float2, tf32 cvt
        const float* src = xp + (size_t)ci * PPAD_;
#pragma unroll
        for (int i = tid; i < 522; i += 256) {
            int kd = i / 174;
            int r2 = i - kd * 174;
            int hh = r2 / 29;
            int w2i = r2 - hh * 29;
            float2 v = *(const float2*)&src[kd * HPWP_ + hh * WP_ + w2i * 2];
            float2 o;
            o.x = __uint_as_float(f2tf32(v.x));
            o.y = __uint_as_float(f2tf32(v.y));
            *(float2*)&slab[kd * 348 + hh * 58 + w2i * 2] = o;
        }
        __syncthreads();

        if (!any_live) continue;   // dead warps skip compute (barriers above are uniform)

#pragma unroll
        for (int ks = 0; ks < 4; ks++) {
            int l0 = lut[ks * 8 + tg];
            int l1 = lut[ks * 8 + tg + 4];
            uint32_t a[2][4];
            if (mt_live0) {
                const float* wr = &Ws[(mw * 32 + gid) * 36 + ks * 8 + tg];
                a[0][0] = __float_as_uint(wr[0]);
                a[0][1] = __float_as_uint(wr[8 * 36]);
                a[0][2] = __float_as_uint(wr[4]);
                a[0][3] = __float_as_uint(wr[8 * 36 + 4]);
            }
            if (mt_live1) {
                const float* wr = &Ws[(mw * 32 + 16 + gid) * 36 + ks * 8 + tg];
                a[1][0] = __float_as_uint(wr[0]);
                a[1][1] = __float_as_uint(wr[8 * 36]);
                a[1][2] = __float_as_uint(wr[4]);
                a[1][3] = __float_as_uint(wr[8 * 36 + 4]);
            }
            int ro = nw * 58 + gid;
#pragma unroll
            for (int nt = 0; nt < 7; nt++) {
                uint32_t b0 = __float_as_uint(slab[l0 + ro]);
                uint32_t b1 = __float_as_uint(slab[l1 + ro]);
                if (mt_live0) mma_tf32(c[0][nt], a[0], b0, b1);
                if (mt_live1) mma_tf32(c[1][nt], a[1], b0, b1);
                ro += 8;
            }
        }
    }

    int hrow = h + nw;
    int pbase = (d * H_ + hrow) * W_;
#pragma unroll
    for (int mt = 0; mt < 2; mt++) {
        int co0 = cot * 64 + mw * 32 + mt * 16 + gid;
#pragma unroll
        for (int half = 0; half < 2; half++) {
            int co = co0 + half * 8;
            if (co < CO_OFF) {
                float bo = b_off[co];
                float* outp = g_off + ((size_t)(n * CO_OFF + co)) * P_ + pbase;
#pragma unroll
                for (int nt = 0; nt < 7; nt++) {
                    int w0 = nt * 8 + tg * 2;
                    float2 st;
                    st.x = c[mt][nt][half * 2 + 0] + bo;
                    st.y = c[mt][nt][half * 2 + 1] + bo;
                    *(float2*)&outp[w0] = st;
                }
            }
        }
    }
}

// ---------------- kernel 2a: deform gather (float4 channel-vectorized) ----
// grid: N*G*K*98 blocks of 256
__global__ __launch_bounds__(256) void deform_gather_kernel() {
    int bx = blockIdx.x;
    int pc = bx % 98;
    int ngk = bx / 98;
    int k = ngk % K_;
    int g = (ngk / K_) % G_;
    int n = ngk / (K_ * G_);
    int p = pc * 256 + threadIdx.x;

    int w = p % W_;
    int h = (p / W_) % H_;
    int d = p / (W_ * H_);

    int kd = k / 9, kh = (k / 3) % 3, kw = k % 3;
    size_t obase = ((size_t)(n * CO_OFF + (g*K_ + k) * 3)) * P_ + p;
    float od = __ldg(&g_off[obase]);
    float oh = __ldg(&g_off[obase + P_]);
    float ow = __ldg(&g_off[obase + 2*(size_t)P_]);

    float pd = (float)(d + kd - 1) + od;
    float ph = (float)(h + kh - 1) + oh;
    float pw = (float)(w + kw - 1) + ow;
    float d0f = floorf(pd), h0f = floorf(ph), w0f = floorf(pw);
    float fd = pd - d0f, fh = ph - h0f, fw = pw - w0f;
    int d0 = (int)d0f, h0 = (int)h0f, w0 = (int)w0f;

    const float4* xg = (const float4*)g_xt + ((size_t)(n * G_ + g)) * P_ * 2;

    float s0=0.f,s1=0.f,s2=0.f,s3=0.f,s4=0.f,s5=0.f,s6=0.f,s7=0.f;
#pragma unroll
    for (int c8 = 0; c8 < 8; c8++) {
        int cd = c8 >> 2, ch = (c8 >> 1) & 1, cw = c8 & 1;
        int id = d0 + cd, ih = h0 + ch, iw = w0 + cw;
        float wt = (cd ? fd : 1.f - fd) * (ch ? fh : 1.f - fh) * (cw ? fw : 1.f - fw);
        bool valid = (id >= 0 && id < D_ && ih >= 0 && ih < H_ && iw >= 0 && iw < W_);
        int idc = min(max(id, 0), D_-1);
        int ihc = min(max(ih, 0), H_-1);
        int iwc = min(max(iw, 0), W_-1);
        int lin = (idc * H_ + ihc) * W_ + iwc;
        wt = valid ? wt : 0.f;
        float4 va = __ldg(&xg[(size_t)lin * 2]);
        float4 vb = __ldg(&xg[(size_t)lin * 2 + 1]);
        s0 += va.x * wt; s1 += va.y * wt; s2 += va.z * wt; s3 += va.w * wt;
        s4 += vb.x * wt; s5 += vb.y * wt; s6 += vb.z * wt; s7 += vb.w * wt;
    }

    float* vout = g_vals + ((size_t)(((n * G_ + g) * K_ + k) * 8)) * P_ + p;
    vout[0]            = s0;
    vout[(size_t)P_]   = s1;
    vout[2*(size_t)P_] = s2;
    vout[3*(size_t)P_] = s3;
    vout[4*(size_t)P_] = s4;
    vout[5*(size_t)P_] = s5;
    vout[6*(size_t)P_] = s6;
    vout[7*(size_t)P_] = s7;
}

// ---------------- kernel 2b: deform GEMM (2-term tf32, 2-tap double stage) -----
// BM=64 x BN=112 (rows h,h+1 of one (n,d)). 128 thr, warps 2M x 2N. grid: 448
__global__ __launch_bounds__(128) void deform_gemm_kernel() {
    __shared__ float WsH[2][64*8];
    __shared__ float BsH[2][8*120];
    __shared__ float BsL[2][8*120];

    int bx = blockIdx.x;
    int hq = bx % 28;
    int h  = hq * 2;
    int d  = (bx / 28) % D_;
    int n  = bx / (28 * D_);

    int tid  = threadIdx.x;
    int lane = tid & 31, warp = tid >> 5;
    int gid  = lane >> 2, tg = lane & 3;
    int mw   = warp >> 1, nw = warp & 1;

    float c[2][7][4];
#pragma unroll
    for (int mt = 0; mt < 2; mt++)
#pragma unroll
        for (int nt = 0; nt < 7; nt++)
#pragma unroll
            for (int i = 0; i < 4; i++) c[mt][nt][i] = 0.f;

    int pbase = (d * H_ + h) * W_;

    for (int t2 = 0; t2 < 108; t2++) {
        __syncthreads();
#pragma unroll
        for (int b = 0; b < 2; b++) {
            int t = t2 * 2 + b;
            {
                float4 vh = ((const float4*)(g_w1H + ((size_t)t << 9)))[tid];
                *(float4*)&WsH[b][tid * 4] = vh;
            }
            const float* vsrc = g_vals + ((size_t)t * 8) * P_ +
                                ((size_t)n * G_ * K_ * 8) * P_ + pbase;
#pragma unroll
            for (int i = tid; i < 224; i += 128) {
                int cl = i / 28, p4 = (i - cl * 28) * 4;
                float4 v = *(const float4*)&vsrc[(size_t)cl * P_ + p4];
                float4 hi, lo;
                hi.x = __uint_as_float(f2tf32(v.x)); lo.x = __uint_as_float(f2tf32(v.x - hi.x));
                hi.y = __uint_as_float(f2tf32(v.y)); lo.y = __uint_as_float(f2tf32(v.y - hi.y));
                hi.z = __uint_as_float(f2tf32(v.z)); lo.z = __uint_as_float(f2tf32(v.z - hi.z));
                hi.w = __uint_as_float(f2tf32(v.w)); lo.w = __uint_as_float(f2tf32(v.w - hi.w));
                *(float4*)&BsH[b][cl * 120 + p4] = hi;
                *(float4*)&BsL[b][cl * 120 + p4] = lo;
            }
        }
        __syncthreads();

#pragma unroll
        for (int b = 0; b < 2; b++) {
            uint32_t aH[2][4];
#pragma unroll
            for (int mt = 0; mt < 2; mt++) {
                int r0 = (mw * 32 + mt * 16 + gid) * 8 + tg * 2;
                float2 vlo = *(const float2*)&WsH[b][r0];
                float2 vhi = *(const float2*)&WsH[b][r0 + 64];
                aH[mt][0] = __float_as_uint(vlo.x);
                aH[mt][1] = __float_as_uint(vhi.x);
                aH[mt][2] = __float_as_uint(vlo.y);
                aH[mt][3] = __float_as_uint(vhi.y);
            }
#pragma unroll
            for (int nt = 0; nt < 7; nt++) {
                int col = nw * 56 + nt * 8 + gid;
                uint32_t b0H = __float_as_uint(BsH[b][tg*120 + col]);
                uint32_t b1H = __float_as_uint(BsH[b][(tg+4)*120 + col]);
                uint32_t b0L = __float_as_uint(BsL[b][tg*120 + col]);
                uint32_t b1L = __float_as_uint(BsL[b][(tg+4)*120 + col]);
#pragma unroll
                for (int mt = 0; mt < 2; mt++) {
                    mma_tf32(c[mt][nt], aH[mt], b0H, b1H);
                    mma_tf32(c[mt][nt], aH[mt], b0L, b1L);
                }
            }
        }
    }

#pragma unroll
    for (int mt = 0; mt < 2; mt++) {
#pragma unroll
        for (int half = 0; half < 2; half++) {
            int o = mw * 32 + mt * 16 + gid + half * 8;
            float* outp = g_y1 + ((size_t)(n * C_ + o)) * P_ + pbase;
#pragma unroll
            for (int nt = 0; nt < 7; nt++) {
                int w0 = nw * 56 + nt * 8 + tg * 2;
                float2 st;
                st.x = c[mt][nt][half * 2 + 0];
                st.y = c[mt][nt][half * 2 + 1];
                *(float2*)&outp[w0] = st;
            }
        }
    }
}

// ---------------- BN statistics (deterministic, one block per channel) ----------------
__global__ void bnstats_kernel(int which) {
    const float* y = which ? g_y3 : g_y1;
    int c = blockIdx.x;
    int tid = threadIdx.x;
    float s = 0.f, s2 = 0.f;
    for (int n = 0; n < N_; n++) {
        const float* p = y + (n * C_ + c) * P_;
        for (int i = tid; i < P_ / 4; i += 256) {
            float4 v = *(const float4*)&p[i * 4];
            s += v.x + v.y + v.z + v.w;
            s2 += v.x*v.x + v.y*v.y + v.z*v.z + v.w*v.w;
        }
    }
    __shared__ float rs[256], rq[256];
    rs[tid] = s; rq[tid] = s2;
    __syncthreads();
    for (int st = 128; st > 0; st >>= 1) {
        if (tid < st) { rs[tid] += rs[tid+st]; rq[tid] += rq[tid+st]; }
        __syncthreads();
    }
    if (tid == 0) {
        float cnt = (float)(N_ * P_);
        float m = rs[0] / cnt;
        float var = rq[0] / cnt - m * m;
        g_stats[which*128 + c]      = m;
        g_stats[which*128 + 64 + c] = rsqrtf(var + 1e-5f);
    }
}

// ---------------- BN1 apply + relu -> padded buffer for conv2 ----------------
__global__ void bnrelu_kernel(const float* __restrict__ gamma, const float* __restrict__ beta) {
    int i4 = blockIdx.x * 256 + threadIdx.x;
    if (i4 >= N_*C_*P_/4) return;
    int idx = i4 * 4;
    int c = (idx / P_) % C_;
    float m = g_stats[c], is = g_stats[64 + c];
    float ga = gamma[c], be = beta[c];
    float4 v = *(const float4*)&g_y1[idx];
    v.x = fmaxf((v.x - m) * is * ga + be, 0.f);
    v.y = fmaxf((v.y - m) * is * ga + be, 0.f);
    v.z = fmaxf((v.z - m) * is * ga + be, 0.f);
    v.w = fmaxf((v.w - m) * is * ga + be, 0.f);
    int pp = idx % P_;
    int w = pp % W_, hh = (pp / W_) % H_, dd = pp / (W_*H_);
    int nc = idx / P_;
    float* dst = &g_y2pad[nc * PPAD_ + (dd+1) * HPWP_ + (hh+1) * WP_ + (w+1)];
    dst[0] = v.x; dst[1] = v.y; dst[2] = v.z; dst[3] = v.w;
}

// ---------------- kernel 5: conv2, 2-term tf32 MMA, 3 blocks/SM -------
__global__ __launch_bounds__(256, 3) void conv2_mma_kernel(const float* __restrict__ b2) {
    __shared__ float Ws[64*36];
    __shared__ float slabH[1044];
    __shared__ float slabL[1044];
    __shared__ int   lut[32];

    int bx = blockIdx.x;
    int hq = bx % 14;
    int h  = hq * 4;
    int d  = (bx / 14) % D_;
    int n  = bx / (14 * D_);

    int tid  = threadIdx.x;
    int lane = tid & 31, warp = tid >> 5;
    int gid  = lane >> 2, tg = lane & 3;
    int mw   = warp >> 2, nw = warp & 3;

    if (tid < 32) {
        int j = tid, base = 0;
        if (j < 27) {
            int kd = j / 9, kh = (j / 3) % 3, kw = j % 3;
            base = kd * 348 + kh * 58 + kw;
        }
        lut[j] = base;
    }

    float c[2][7][4];
#pragma unroll
    for (int mt = 0; mt < 2; mt++)
#pragma unroll
        for (int nt = 0; nt < 7; nt++)
#pragma unroll
            for (int i = 0; i < 4; i++) c[mt][nt][i] = 0.f;

    const float* xp = g_y2pad + n * (C_*PPAD_) + d * HPWP_ + h * WP_;

    for (int ci = 0; ci < C_; ci++) {
        __syncthreads();
        const float4* wh4 = (const float4*)(g_w2H + ((size_t)ci << 11));
#pragma unroll
        for (int i = tid; i < 512; i += 256) {
            float4 vh = wh4[i];
            int co = i >> 3, j4 = (i & 7) * 4;
            *(float4*)&Ws[co * 36 + j4] = vh;
        }
        const float* src = xp + (size_t)ci * PPAD_;
#pragma unroll
        for (int i = tid; i < 522; i += 256) {
            int kd = i / 174;
            int r2 = i - kd * 174;
            int hh = r2 / 29;
            int w2i = r2 - hh * 29;
            float2 v = *(const float2*)&src[kd * HPWP_ + hh * WP_ + w2i * 2];
            float2 hi, lo;
            hi.x = __uint_as_float(f2tf32(v.x)); lo.x = __uint_as_float(f2tf32(v.x - hi.x));
            hi.y = __uint_as_float(f2tf32(v.y)); lo.y = __uint_as_float(f2tf32(v.y - hi.y));
            int so = kd * 348 + hh * 58 + w2i * 2;
            *(float2*)&slabH[so] = hi;
            *(float2*)&slabL[so] = lo;
        }
        __syncthreads();

#pragma unroll
        for (int ks = 0; ks < 4; ks++) {
            int l0 = lut[ks * 8 + tg];
            int l1 = lut[ks * 8 + tg + 4];
            uint32_t aH[2][4];
#pragma unroll
            for (int mt = 0; mt < 2; mt++) {
                const float* wr = &Ws[(mw * 32 + mt * 16 + gid) * 36 + ks * 8 + tg];
                aH[mt][0] = __float_as_uint(wr[0]);
                aH[mt][1] = __float_as_uint(wr[8 * 36]);
                aH[mt][2] = __float_as_uint(wr[4]);
                aH[mt][3] = __float_as_uint(wr[8 * 36 + 4]);
            }
            int ro = nw * 58 + gid;
#pragma unroll
            for (int nt = 0; nt < 7; nt++) {
                uint32_t bH0 = __float_as_uint(slabH[l0 + ro]);
                uint32_t bH1 = __float_as_uint(slabH[l1 + ro]);
                uint32_t bL0 = __float_as_uint(slabL[l0 + ro]);
                uint32_t bL1 = __float_as_uint(slabL[l1 + ro]);
#pragma unroll
                for (int mt = 0; mt < 2; mt++) {
                    mma_tf32(c[mt][nt], aH[mt], bH0, bH1);
                    mma_tf32(c[mt][nt], aH[mt], bL0, bL1);
                }
                ro += 8;
            }
        }
    }

    int hrow = h + nw;
    int pbase = (d * H_ + hrow) * W_;
#pragma unroll
    for (int mt = 0; mt < 2; mt++) {
        int co0 = mw * 32 + mt * 16 + gid;
#pragma unroll
        for (int half = 0; half < 2; half++) {
            int co = co0 + half * 8;
            float bo = b2[co];
            float* outp = g_y3 + ((size_t)(n * C_ + co)) * P_ + pbase;
#pragma unroll
            for (int nt = 0; nt < 7; nt++) {
                int w0 = nt * 8 + tg * 2;
                float2 st;
                st.x = c[mt][nt][half * 2 + 0] + bo;
                st.y = c[mt][nt][half * 2 + 1] + bo;
                *(float2*)&outp[w0] = st;
            }
        }
    }
}

// ---------------- final: bn2 + residual + relu (float4) ----------------
__global__ void final_kernel(const float* __restrict__ x,
                             const float* __restrict__ gamma2,
                             const float* __restrict__ beta2,
                             float* __restrict__ out) {
    int i4 = blockIdx.x * 256 + threadIdx.x;
    if (i4 >= N_*C_*P_/4) return;
    int idx = i4 * 4;
    int c = (idx / P_) % C_;
    float m = g_stats[128 + c], is = g_stats[192 + c];
    float ga = gamma2[c], be = beta2[c];
    float4 v = *(const float4*)&g_y3[idx];
    float4 xr = *(const float4*)&x[idx];
    float4 o;
    o.x = fmaxf((v.x - m) * is * ga + be + xr.x, 0.f);
    o.y = fmaxf((v.y - m) * is * ga + be + xr.y, 0.f);
    o.z = fmaxf((v.z - m) * is * ga + be + xr.z, 0.f);
    o.w = fmaxf((v.w - m) * is * ga + be + xr.w, 0.f);
    *(float4*)&out[idx] = o;
}

// ---------------- launcher ----------------
extern "C" void kernel_launch(void* const* d_in, const int* in_sizes, int n_in,
                              void* d_out, int out_size) {
    const float* x      = (const float*)d_in[0];
    const float* w_off  = (const float*)d_in[1];
    const float* b_off  = (const float*)d_in[2];
    const float* w1     = (const float*)d_in[3];
    const float* gamma1 = (const float*)d_in[4];
    const float* beta1  = (const float*)d_in[5];
    const float* w2     = (const float*)d_in[6];
    const float* b2     = (const float*)d_in[7];
    const float* gamma2 = (const float*)d_in[8];
    const float* beta2  = (const float*)d_in[9];
    float* out = (float*)d_out;

    int padtot = N_*C_*PPAD_;
    int tot4 = N_*C_*P_/4;

    prep_kernel<<<(PREP_TOT + 255) / 256, 256>>>(w_off, w1, w2);
    padinit_kernel<<<(padtot + 255) / 256, 256>>>(x);
    transpose_kernel<<<(N_*G_*P_ + 255) / 256, 256>>>(x);
    offconv_mma_kernel<<<dim3(224, 11), 256>>>(b_off);
    deform_gather_kernel<<<N_*G_*K_*98, 256>>>();
    deform_gemm_kernel<<<448, 128>>>();
    bnstats_kernel<<<64, 256>>>(0);
    bnrelu_kernel<<<(tot4 + 255) / 256, 256>>>(gamma1, beta1);
    conv2_mma_kernel<<<224, 256>>>(b2);
    bnstats_kernel<<<64, 256>>>(1);
    final_kernel<<<(tot4 + 255) / 256, 256>>>(x, gamma2, beta2, out);
}

// round 13
// speedup vs baseline: 1.1803x; 1.1803x over previous
#include <cuda_runtime.h>
#include <cuda_fp16.h>
#include <cstdint>

#define N_ 2
#define C_ 64
#define D_ 8
#define H_ 56
#define W_ 56
#define G_ 8
#define K_ 27
#define CO_OFF 648
#define P_ (D_*H_*W_)          // 25088
#define DP_ (D_+2)
#define HP_ (H_+2)
#define WP_ (W_+2)
#define PPAD_ (DP_*HP_*WP_)    // 33640
#define HPWP_ (HP_*WP_)
#define KTOT 1728              // 64 ci * 27 taps

#define PREP_W0H (704*KTOT)    // 1216512 fp16 weights (648 real, pad to 704)
#define PREP_W1 (216*64*8)     // 110592
#define PREP_W2 (64*64*32)     // 131072

// ---------------- scratch (no allocation allowed) ----------------
__device__ float g_xpad[N_*C_*PPAD_];    // padded input
__device__ float g_y2pad[N_*C_*PPAD_];   // padded bn1+relu output for conv2
__device__ float g_off[N_*CO_OFF*P_];    // offset tensor (130 MB)
__device__ float4 g_xt[N_*G_*P_*2];      // x transposed [n][g][p][8ch]
__device__ float g_vals[N_*G_*K_*8*P_];  // sampled values (347 MB)
__device__ float g_y1[N_*C_*P_];         // deform conv output
__device__ float g_y3[N_*C_*P_];         // conv2 output
__device__ float g_stats[4*C_];          // mean1, istd1, mean2, istd2
__device__ __half g_woffh[PREP_W0H];     // fp16 w_off [cog 704][k 1728]
__device__ __half g_xc[(size_t)N_*KTOT*P_]; // im2col fp16 [n][k][p] (173 MB)
__device__ float g_w1H[PREP_W1];         // w1 tf32 [t][o][cl'] (pair-permuted)
__device__ float g_w2H[PREP_W2];         // w2 tf32 [ci][co][j32]

// ---------------- helpers ----------------
__device__ __forceinline__ uint32_t f2tf32(float x) {
    uint32_t r;
    asm("cvt.rna.tf32.f32 %0, %1;" : "=r"(r) : "f"(x));
    return r;
}

__device__ __forceinline__ void mma_tf32(float c[4], const uint32_t a[4],
                                         uint32_t b0, uint32_t b1) {
    asm volatile(
        "mma.sync.aligned.m16n8k8.row.col.f32.tf32.tf32.f32 "
        "{%0,%1,%2,%3}, {%4,%5,%6,%7}, {%8,%9}, {%0,%1,%2,%3};"
        : "+f"(c[0]), "+f"(c[1]), "+f"(c[2]), "+f"(c[3])
        : "r"(a[0]), "r"(a[1]), "r"(a[2]), "r"(a[3]), "r"(b0), "r"(b1));
}

__device__ __forceinline__ void mma_fp16(float c[4], const uint32_t a[4],
                                         uint32_t b0, uint32_t b1) {
    asm volatile(
        "mma.sync.aligned.m16n8k16.row.col.f32.f16.f16.f32 "
        "{%0,%1,%2,%3}, {%4,%5,%6,%7}, {%8,%9}, {%0,%1,%2,%3};"
        : "+f"(c[0]), "+f"(c[1]), "+f"(c[2]), "+f"(c[3])
        : "r"(a[0]), "r"(a[1]), "r"(a[2]), "r"(a[3]), "r"(b0), "r"(b1));
}

// ---------------- kernel P: weight prep ----------------
__global__ void prep_kernel(const float* __restrict__ w_off,
                            const float* __restrict__ w1,
                            const float* __restrict__ w2) {
    int idx = blockIdx.x * 256 + threadIdx.x;
    if (idx < PREP_W0H) {
        int k = idx % KTOT, cog = idx / KTOT;
        float v = (cog < CO_OFF) ? w_off[(size_t)cog * KTOT + k] : 0.f;
        g_woffh[idx] = __float2half_rn(v);
    } else if (idx < PREP_W0H + PREP_W1) {
        int r = idx - PREP_W0H;
        int clp = r & 7, o = (r >> 3) & 63, t = r >> 9;
        int cl = (clp >> 1) + (clp & 1) * 4;
        int g = t / 27, k = t - g * 27;
        float v = w1[(o * C_ + g * 8 + cl) * K_ + k];
        g_w1H[r] = __uint_as_float(f2tf32(v));
    } else if (idx < PREP_W0H + PREP_W1 + PREP_W2) {
        int r = idx - PREP_W0H - PREP_W1;
        int j = r & 31, co = (r >> 5) & 63, ci = r >> 11;
        float v = (j < 27) ? w2[(co * C_ + ci) * 27 + j] : 0.f;
        g_w2H[r] = __uint_as_float(f2tf32(v));
    }
}

// ---------------- kernel T: transpose x -> [n][g][p][8ch] ----------------
__global__ void transpose_kernel(const float* __restrict__ x) {
    int idx = blockIdx.x * 256 + threadIdx.x;
    if (idx >= N_*G_*P_) return;
    int p = idx % P_;
    int g = (idx / P_) % G_;
    int n = idx / (P_ * G_);
    const float* xs = x + ((size_t)(n * C_ + g * 8)) * P_ + p;
    float4 a, b;
    a.x = xs[0];            a.y = xs[(size_t)P_];
    a.z = xs[2*(size_t)P_]; a.w = xs[3*(size_t)P_];
    b.x = xs[4*(size_t)P_]; b.y = xs[5*(size_t)P_];
    b.z = xs[6*(size_t)P_]; b.w = xs[7*(size_t)P_];
    g_xt[(size_t)idx * 2]     = a;
    g_xt[(size_t)idx * 2 + 1] = b;
}

// ---------------- kernel 0: build padded x ----------------
__global__ void padinit_kernel(const float* __restrict__ x) {
    int idx = blockIdx.x * 256 + threadIdx.x;
    if (idx >= N_*C_*PPAD_) return;
    int wp = idx % WP_;
    int hp = (idx / WP_) % HP_;
    int dp = (idx / (WP_*HP_)) % DP_;
    int nc = idx / PPAD_;
    bool interior = (dp >= 1 && dp <= D_ && hp >= 1 && hp <= H_ && wp >= 1 && wp <= W_);
    float v = 0.f;
    if (interior)
        v = x[nc * P_ + (dp-1) * (H_*W_) + (hp-1) * W_ + (wp-1)];
    g_xpad[idx] = v;
    if (!interior) g_y2pad[idx] = 0.f;
}

// ---------------- kernel I: im2col fp16  Xc[n][k][p] ----------------
// thread handles 8 consecutive p (one w-octet). grid: 42336 x 256
__global__ void im2col_kernel() {
    int idx = blockIdx.x * 256 + threadIdx.x;
    if (idx >= N_ * KTOT * (P_ / 8)) return;
    int p8 = idx % (P_ / 8);
    int k  = (idx / (P_ / 8)) % KTOT;
    int n  = idx / ((P_ / 8) * KTOT);
    int ci = k / 27, tap = k - ci * 27;
    int kd = tap / 9, kh = (tap / 3) % 3, kw = tap % 3;
    int w8 = (p8 % 7) * 8;
    int h  = (p8 / 7) % H_;
    int d  = p8 / 392;
    const float* src = g_xpad + (size_t)(n * C_ + ci) * PPAD_
                       + (d + kd) * HPWP_ + (h + kh) * WP_ + (w8 + kw);
    __half out[8];
#pragma unroll
    for (int j = 0; j < 8; j++) out[j] = __float2half_rn(src[j]);
    *(uint4*)(g_xc + ((size_t)(n * KTOT + k)) * P_ + p8 * 8) = *(const uint4*)out;
}

// ---------------- kernel 1: offset conv, fp16 m16n8k16 dense GEMM --------------
// out[648, P] = Wh[648,1728] x Xc[1728, P].  BM=64, BN=112, 128 thr (warps 2M x 2N).
// grid: (448 = n*224 pos-tiles, 11 co-tiles)
__global__ __launch_bounds__(128) void offconv_fp16_kernel(const float* __restrict__ b_off) {
    __shared__ uint32_t Wsu[64*36];   // fp16 pairs [co][36 u32] (row=72 halves, 144B: STS.128 ok)
    __shared__ uint32_t Bsu[32*120];  // k-pair interleaved [kp][120 pos] (banks all-distinct)

    int bx = blockIdx.x;
    int pt = bx % 224;
    int n  = bx / 224;
    int pbase = pt * 112;
    int cot = blockIdx.y;

    int tid  = threadIdx.x;
    int lane = tid & 31, warp = tid >> 5;
    int gid  = lane >> 2, tg = lane & 3;
    int mw   = warp >> 1, nw = warp & 1;

    float c[2][7][4];
#pragma unroll
    for (int mt = 0; mt < 2; mt++)
#pragma unroll
        for (int nt = 0; nt < 7; nt++)
#pragma unroll
            for (int i = 0; i < 4; i++) c[mt][nt][i] = 0.f;

    for (int kc = 0; kc < 27; kc++) {
        int k0 = kc * 64;
        __syncthreads();
        // stage Ws: 64 rows x 64 halves (8 uint4 each) = 512 uint4, 4 per thread
#pragma unroll
        for (int i = tid; i < 512; i += 128) {
            int co = i >> 3, f = i & 7;
            uint4 v = *(const uint4*)(g_woffh + ((size_t)(cot * 64 + co)) * KTOT + k0 + f * 8);
            *(uint4*)&Wsu[co * 36 + f * 4] = v;
        }
        // stage Bs2: 32 k-pairs x 14 pos-octets; interleave rows 2kp/2kp+1 into half2
#pragma unroll
        for (int i = tid; i < 448; i += 128) {
            int kp = i / 14, pg = i - kp * 14;
            int pos0 = pg * 8;
            const __half* r0 = g_xc + ((size_t)(n * KTOT + k0 + 2 * kp)) * P_ + pbase + pos0;
            uint4 a = *(const uint4*)r0;
            uint4 b = *(const uint4*)(r0 + P_);
            uint32_t o0 = __byte_perm(a.x, b.x, 0x5410), o1 = __byte_perm(a.x, b.x, 0x7632);
            uint32_t o2 = __byte_perm(a.y, b.y, 0x5410), o3 = __byte_perm(a.y, b.y, 0x7632);
            uint32_t o4 = __byte_perm(a.z, b.z, 0x5410), o5 = __byte_perm(a.z, b.z, 0x7632);
            uint32_t o6 = __byte_perm(a.w, b.w, 0x5410), o7 = __byte_perm(a.w, b.w, 0x7632);
            int base = kp * 120 + pos0;
            uint4 u0; u0.x = o0; u0.y = o1; u0.z = o2; u0.w = o3;
            uint4 u1; u1.x = o4; u1.y = o5; u1.z = o6; u1.w = o7;
            *(uint4*)&Bsu[base]     = u0;
            *(uint4*)&Bsu[base + 4] = u1;
        }
        __syncthreads();

#pragma unroll
        for (int ks = 0; ks < 4; ks++) {
            uint32_t a[2][4];
#pragma unroll
            for (int mt = 0; mt < 2; mt++) {
                int r = mw * 32 + mt * 16 + gid;
                a[mt][0] = Wsu[r * 36 + ks * 8 + tg];            // row gid,  k lo
                a[mt][1] = Wsu[(r + 8) * 36 + ks * 8 + tg];      // row gid+8, k lo
                a[mt][2] = Wsu[r * 36 + ks * 8 + tg + 4];        // row gid,  k hi
                a[mt][3] = Wsu[(r + 8) * 36 + ks * 8 + tg + 4];  // row gid+8, k hi
            }
#pragma unroll
            for (int nt = 0; nt < 7; nt++) {
                int col = nw * 56 + nt * 8 + gid;
                uint32_t b0 = Bsu[(ks * 8 + tg) * 120 + col];
                uint32_t b1 = Bsu[(ks * 8 + tg + 4) * 120 + col];
                mma_fp16(c[0][nt], a[0], b0, b1);
                mma_fp16(c[1][nt], a[1], b0, b1);
            }
        }
    }

#pragma unroll
    for (int mt = 0; mt < 2; mt++) {
#pragma unroll
        for (int half = 0; half < 2; half++) {
            int co = cot * 64 + mw * 32 + mt * 16 + gid + half * 8;
            if (co < CO_OFF) {
                float bo = b_off[co];
                float* outp = g_off + ((size_t)(n * CO_OFF + co)) * P_ + pbase;
#pragma unroll
                for (int nt = 0; nt < 7; nt++) {
                    int w0 = nw * 56 + nt * 8 + tg * 2;
                    float2 st;
                    st.x = c[mt][nt][half * 2 + 0] + bo;
                    st.y = c[mt][nt][half * 2 + 1] + bo;
                    *(float2*)&outp[w0] = st;
                }
            }
        }
    }
}

// ---------------- kernel 2a: deform gather (float4 channel-vectorized) ----
__global__ __launch_bounds__(256) void deform_gather_kernel() {
    int bx = blockIdx.x;
    int pc = bx % 98;
    int ngk = bx / 98;
    int k = ngk % K_;
    int g = (ngk / K_) % G_;
    int n = ngk / (K_ * G_);
    int p = pc * 256 + threadIdx.x;

    int w = p % W_;
    int h = (p / W_) % H_;
    int d = p / (W_ * H_);

    int kd = k / 9, kh = (k / 3) % 3, kw = k % 3;
    size_t obase = ((size_t)(n * CO_OFF + (g*K_ + k) * 3)) * P_ + p;
    float od = __ldg(&g_off[obase]);
    float oh = __ldg(&g_off[obase + P_]);
    float ow = __ldg(&g_off[obase + 2*(size_t)P_]);

    float pd = (float)(d + kd - 1) + od;
    float ph = (float)(h + kh - 1) + oh;
    float pw = (float)(w + kw - 1) + ow;
    float d0f = floorf(pd), h0f = floorf(ph), w0f = floorf(pw);
    float fd = pd - d0f, fh = ph - h0f, fw = pw - w0f;
    int d0 = (int)d0f, h0 = (int)h0f, w0 = (int)w0f;

    const float4* xg = (const float4*)g_xt + ((size_t)(n * G_ + g)) * P_ * 2;

    float s0=0.f,s1=0.f,s2=0.f,s3=0.f,s4=0.f,s5=0.f,s6=0.f,s7=0.f;
#pragma unroll
    for (int c8 = 0; c8 < 8; c8++) {
        int cd = c8 >> 2, ch = (c8 >> 1) & 1, cw = c8 & 1;
        int id = d0 + cd, ih = h0 + ch, iw = w0 + cw;
        float wt = (cd ? fd : 1.f - fd) * (ch ? fh : 1.f - fh) * (cw ? fw : 1.f - fw);
        bool valid = (id >= 0 && id < D_ && ih >= 0 && ih < H_ && iw >= 0 && iw < W_);
        int idc = min(max(id, 0), D_-1);
        int ihc = min(max(ih, 0), H_-1);
        int iwc = min(max(iw, 0), W_-1);
        int lin = (idc * H_ + ihc) * W_ + iwc;
        wt = valid ? wt : 0.f;
        float4 va = __ldg(&xg[(size_t)lin * 2]);
        float4 vb = __ldg(&xg[(size_t)lin * 2 + 1]);
        s0 += va.x * wt; s1 += va.y * wt; s2 += va.z * wt; s3 += va.w * wt;
        s4 += vb.x * wt; s5 += vb.y * wt; s6 += vb.z * wt; s7 += vb.w * wt;
    }

    float* vout = g_vals + ((size_t)(((n * G_ + g) * K_ + k) * 8)) * P_ + p;
    vout[0]            = s0;
    vout[(size_t)P_]   = s1;
    vout[2*(size_t)P_] = s2;
    vout[3*(size_t)P_] = s3;
    vout[4*(size_t)P_] = s4;
    vout[5*(size_t)P_] = s5;
    vout[6*(size_t)P_] = s6;
    vout[7*(size_t)P_] = s7;
}

// ---------------- kernel 2b: deform GEMM (2-term tf32, 2-tap double stage) -----
__global__ __launch_bounds__(128) void deform_gemm_kernel() {
    __shared__ float WsH[2][64*8];
    __shared__ float BsH[2][8*120];
    __shared__ float BsL[2][8*120];

    int bx = blockIdx.x;
    int hq = bx % 28;
    int h  = hq * 2;
    int d  = (bx / 28) % D_;
    int n  = bx / (28 * D_);

    int tid  = threadIdx.x;
    int lane = tid & 31, warp = tid >> 5;
    int gid  = lane >> 2, tg = lane & 3;
    int mw   = warp >> 1, nw = warp & 1;

    float c[2][7][4];
#pragma unroll
    for (int mt = 0; mt < 2; mt++)
#pragma unroll
        for (int nt = 0; nt < 7; nt++)
#pragma unroll
            for (int i = 0; i < 4; i++) c[mt][nt][i] = 0.f;

    int pbase = (d * H_ + h) * W_;

    for (int t2 = 0; t2 < 108; t2++) {
        __syncthreads();
#pragma unroll
        for (int b = 0; b < 2; b++) {
            int t = t2 * 2 + b;
            {
                float4 vh = ((const float4*)(g_w1H + ((size_t)t << 9)))[tid];
                *(float4*)&WsH[b][tid * 4] = vh;
            }
            const float* vsrc = g_vals + ((size_t)t * 8) * P_ +
                                ((size_t)n * G_ * K_ * 8) * P_ + pbase;
#pragma unroll
            for (int i = tid; i < 224; i += 128) {
                int cl = i / 28, p4 = (i - cl * 28) * 4;
                float4 v = *(const float4*)&vsrc[(size_t)cl * P_ + p4];
                float4 hi, lo;
                hi.x = __uint_as_float(f2tf32(v.x)); lo.x = __uint_as_float(f2tf32(v.x - hi.x));
                hi.y = __uint_as_float(f2tf32(v.y)); lo.y = __uint_as_float(f2tf32(v.y - hi.y));
                hi.z = __uint_as_float(f2tf32(v.z)); lo.z = __uint_as_float(f2tf32(v.z - hi.z));
                hi.w = __uint_as_float(f2tf32(v.w)); lo.w = __uint_as_float(f2tf32(v.w - hi.w));
                *(float4*)&BsH[b][cl * 120 + p4] = hi;
                *(float4*)&BsL[b][cl * 120 + p4] = lo;
            }
        }
        __syncthreads();

#pragma unroll
        for (int b = 0; b < 2; b++) {
            uint32_t aH[2][4];
#pragma unroll
            for (int mt = 0; mt < 2; mt++) {
                int r0 = (mw * 32 + mt * 16 + gid) * 8 + tg * 2;
                float2 vlo = *(const float2*)&WsH[b][r0];
                float2 vhi = *(const float2*)&WsH[b][r0 + 64];
                aH[mt][0] = __float_as_uint(vlo.x);
                aH[mt][1] = __float_as_uint(vhi.x);
                aH[mt][2] = __float_as_uint(vlo.y);
                aH[mt][3] = __float_as_uint(vhi.y);
            }
#pragma unroll
            for (int nt = 0; nt < 7; nt++) {
                int col = nw * 56 + nt * 8 + gid;
                uint32_t b0H = __float_as_uint(BsH[b][tg*120 + col]);
                uint32_t b1H = __float_as_uint(BsH[b][(tg+4)*120 + col]);
                uint32_t b0L = __float_as_uint(BsL[b][tg*120 + col]);
                uint32_t b1L = __float_as_uint(BsL[b][(tg+4)*120 + col]);
#pragma unroll
                for (int mt = 0; mt < 2; mt++) {
                    mma_tf32(c[mt][nt], aH[mt], b0H, b1H);
                    mma_tf32(c[mt][nt], aH[mt], b0L, b1L);
                }
            }
        }
    }

#pragma unroll
    for (int mt = 0; mt < 2; mt++) {
#pragma unroll
        for (int half = 0; half < 2; half++) {
            int o = mw * 32 + mt * 16 + gid + half * 8;
            float* outp = g_y1 + ((size_t)(n * C_ + o)) * P_ + pbase;
#pragma unroll
            for (int nt = 0; nt < 7; nt++) {
                int w0 = nw * 56 + nt * 8 + tg * 2;
                float2 st;
                st.x = c[mt][nt][half * 2 + 0];
                st.y = c[mt][nt][half * 2 + 1];
                *(float2*)&outp[w0] = st;
            }
        }
    }
}

// ---------------- BN statistics ----------------
__global__ void bnstats_kernel(int which) {
    const float* y = which ? g_y3 : g_y1;
    int c = blockIdx.x;
    int tid = threadIdx.x;
    float s = 0.f, s2 = 0.f;
    for (int n = 0; n < N_; n++) {
        const float* p = y + (n * C_ + c) * P_;
        for (int i = tid; i < P_ / 4; i += 256) {
            float4 v = *(const float4*)&p[i * 4];
            s += v.x + v.y + v.z + v.w;
            s2 += v.x*v.x + v.y*v.y + v.z*v.z + v.w*v.w;
        }
    }
    __shared__ float rs[256], rq[256];
    rs[tid] = s; rq[tid] = s2;
    __syncthreads();
    for (int st = 128; st > 0; st >>= 1) {
        if (tid < st) { rs[tid] += rs[tid+st]; rq[tid] += rq[tid+st]; }
        __syncthreads();
    }
    if (tid == 0) {
        float cnt = (float)(N_ * P_);
        float m = rs[0] / cnt;
        float var = rq[0] / cnt - m * m;
        g_stats[which*128 + c]      = m;
        g_stats[which*128 + 64 + c] = rsqrtf(var + 1e-5f);
    }
}

// ---------------- BN1 apply + relu -> padded buffer ----------------
__global__ void bnrelu_kernel(const float* __restrict__ gamma, const float* __restrict__ beta) {
    int i4 = blockIdx.x * 256 + threadIdx.x;
    if (i4 >= N_*C_*P_/4) return;
    int idx = i4 * 4;
    int c = (idx / P_) % C_;
    float m = g_stats[c], is = g_stats[64 + c];
    float ga = gamma[c], be = beta[c];
    float4 v = *(const float4*)&g_y1[idx];
    v.x = fmaxf((v.x - m) * is * ga + be, 0.f);
    v.y = fmaxf((v.y - m) * is * ga + be, 0.f);
    v.z = fmaxf((v.z - m) * is * ga + be, 0.f);
    v.w = fmaxf((v.w - m) * is * ga + be, 0.f);
    int pp = idx % P_;
    int w = pp % W_, hh = (pp / W_) % H_, dd = pp / (W_*H_);
    int nc = idx / P_;
    float* dst = &g_y2pad[nc * PPAD_ + (dd+1) * HPWP_ + (hh+1) * WP_ + (w+1)];
    dst[0] = v.x; dst[1] = v.y; dst[2] = v.z; dst[3] = v.w;
}

// ---------------- kernel 5: conv2, 2-term tf32 MMA ----------------
__global__ __launch_bounds__(256, 3) void conv2_mma_kernel(const float* __restrict__ b2) {
    __shared__ float Ws[64*36];
    __shared__ float slabH[1044];
    __shared__ float slabL[1044];
    __shared__ int   lut[32];

    int bx = blockIdx.x;
    int hq = bx % 14;
    int h  = hq * 4;
    int d  = (bx / 14) % D_;
    int n  = bx / (14 * D_);

    int tid  = threadIdx.x;
    int lane = tid & 31, warp = tid >> 5;
    int gid  = lane >> 2, tg = lane & 3;
    int mw   = warp >> 2, nw = warp & 3;

    if (tid < 32) {
        int j = tid, base = 0;
        if (j < 27) {
            int kd = j / 9, kh = (j / 3) % 3, kw = j % 3;
            base = kd * 348 + kh * 58 + kw;
        }
        lut[j] = base;
    }

    float c[2][7][4];
#pragma unroll
    for (int mt = 0; mt < 2; mt++)
#pragma unroll
        for (int nt = 0; nt < 7; nt++)
#pragma unroll
            for (int i = 0; i < 4; i++) c[mt][nt][i] = 0.f;

    const float* xp = g_y2pad + n * (C_*PPAD_) + d * HPWP_ + h * WP_;

    for (int ci = 0; ci < C_; ci++) {
        __syncthreads();
        const float4* wh4 = (const float4*)(g_w2H + ((size_t)ci << 11));
#pragma unroll
        for (int i = tid; i < 512; i += 256) {
            float4 vh = wh4[i];
            int co = i >> 3, j4 = (i & 7) * 4;
            *(float4*)&Ws[co * 36 + j4] = vh;
        }
        const float* src = xp + (size_t)ci * PPAD_;
#pragma unroll
        for (int i = tid; i < 522; i += 256) {
            int kd = i / 174;
            int r2 = i - kd * 174;
            int hh = r2 / 29;
            int w2i = r2 - hh * 29;
            float2 v = *(const float2*)&src[kd * HPWP_ + hh * WP_ + w2i * 2];
            float2 hi, lo;
            hi.x = __uint_as_float(f2tf32(v.x)); lo.x = __uint_as_float(f2tf32(v.x - hi.x));
            hi.y = __uint_as_float(f2tf32(v.y)); lo.y = __uint_as_float(f2tf32(v.y - hi.y));
            int so = kd * 348 + hh * 58 + w2i * 2;
            *(float2*)&slabH[so] = hi;
            *(float2*)&slabL[so] = lo;
        }
        __syncthreads();

#pragma unroll
        for (int ks = 0; ks < 4; ks++) {
            int l0 = lut[ks * 8 + tg];
            int l1 = lut[ks * 8 + tg + 4];
            uint32_t aH[2][4];
#pragma unroll
            for (int mt = 0; mt < 2; mt++) {
                const float* wr = &Ws[(mw * 32 + mt * 16 + gid) * 36 + ks * 8 + tg];
                aH[mt][0] = __float_as_uint(wr[0]);
                aH[mt][1] = __float_as_uint(wr[8 * 36]);
                aH[mt][2] = __float_as_uint(wr[4]);
                aH[mt][3] = __float_as_uint(wr[8 * 36 + 4]);
            }
            int ro = nw * 58 + gid;
#pragma unroll
            for (int nt = 0; nt < 7; nt++) {
                uint32_t bH0 = __float_as_uint(slabH[l0 + ro]);
                uint32_t bH1 = __float_as_uint(slabH[l1 + ro]);
                uint32_t bL0 = __float_as_uint(slabL[l0 + ro]);
                uint32_t bL1 = __float_as_uint(slabL[l1 + ro]);
#pragma unroll
                for (int mt = 0; mt < 2; mt++) {
                    mma_tf32(c[mt][nt], aH[mt], bH0, bH1);
                    mma_tf32(c[mt][nt], aH[mt], bL0, bL1);
                }
                ro += 8;
            }
        }
    }

    int hrow = h + nw;
    int pbase = (d * H_ + hrow) * W_;
#pragma unroll
    for (int mt = 0; mt < 2; mt++) {
        int co0 = mw * 32 + mt * 16 + gid;
#pragma unroll
        for (int half = 0; half < 2; half++) {
            int co = co0 + half * 8;
            float bo = b2[co];
            float* outp = g_y3 + ((size_t)(n * C_ + co)) * P_ + pbase;
#pragma unroll
            for (int nt = 0; nt < 7; nt++) {
                int w0 = nt * 8 + tg * 2;
                float2 st;
                st.x = c[mt][nt][half * 2 + 0] + bo;
                st.y = c[mt][nt][half * 2 + 1] + bo;
                *(float2*)&outp[w0] = st;
            }
        }
    }
}

// ---------------- final: bn2 + residual + relu (float4) ----------------
__global__ void final_kernel(const float* __restrict__ x,
                             const float* __restrict__ gamma2,
                             const float* __restrict__ beta2,
                             float* __restrict__ out) {
    int i4 = blockIdx.x * 256 + threadIdx.x;
    if (i4 >= N_*C_*P_/4) return;
    int idx = i4 * 4;
    int c = (idx / P_) % C_;
    float m = g_stats[128 + c], is = g_stats[192 + c];
    float ga = gamma2[c], be = beta2[c];
    float4 v = *(const float4*)&g_y3[idx];
    float4 xr = *(const float4*)&x[idx];
    float4 o;
    o.x = fmaxf((v.x - m) * is * ga + be + xr.x, 0.f);
    o.y = fmaxf((v.y - m) * is * ga + be + xr.y, 0.f);
    o.z = fmaxf((v.z - m) * is * ga + be + xr.z, 0.f);
    o.w = fmaxf((v.w - m) * is * ga + be + xr.w, 0.f);
    *(float4*)&out[idx] = o;
}

// ---------------- launcher ----------------
extern "C" void kernel_launch(void* const* d_in, const int* in_sizes, int n_in,
                              void* d_out, int out_size) {
    const float* x      = (const float*)d_in[0];
    const float* w_off  = (const float*)d_in[1];
    const float* b_off  = (const float*)d_in[2];
    const float* w1     = (const float*)d_in[3];
    const float* gamma1 = (const float*)d_in[4];
    const float* beta1  = (const float*)d_in[5];
    const float* w2     = (const float*)d_in[6];
    const float* b2     = (const float*)d_in[7];
    const float* gamma2 = (const float*)d_in[8];
    const float* beta2  = (const float*)d_in[9];
    float* out = (float*)d_out;

    int padtot = N_*C_*PPAD_;
    int tot4 = N_*C_*P_/4;
    int preptot = PREP_W0H + PREP_W1 + PREP_W2;
    int im2tot = N_ * KTOT * (P_ / 8);

    prep_kernel<<<(preptot + 255) / 256, 256>>>(w_off, w1, w2);
    padinit_kernel<<<(padtot + 255) / 256, 256>>>(x);
    transpose_kernel<<<(N_*G_*P_ + 255) / 256, 256>>>(x);
    im2col_kernel<<<(im2tot + 255) / 256, 256>>>();
    offconv_fp16_kernel<<<dim3(448, 11), 128>>>(b_off);
    deform_gather_kernel<<<N_*G_*K_*98, 256>>>();
    deform_gemm_kernel<<<448, 128>>>();
    bnstats_kernel<<<64, 256>>>(0);
    bnrelu_kernel<<<(tot4 + 255) / 256, 256>>>(gamma1, beta1);
    conv2_mma_kernel<<<224, 256>>>(b2);
    bnstats_kernel<<<64, 256>>>(1);
    final_kernel<<<(tot4 + 255) / 256, 256>>>(x, gamma2, beta2, out);
}

// round 14
// speedup vs baseline: 1.4187x; 1.2020x over previous
#include <cuda_runtime.h>
#include <cuda_fp16.h>
#include <cstdint>

#define N_ 2
#define C_ 64
#define D_ 8
#define H_ 56
#define W_ 56
#define G_ 8
#define K_ 27
#define CO_OFF 648
#define P_ (D_*H_*W_)          // 25088
#define DP_ (D_+2)
#define HP_ (H_+2)
#define WP_ (W_+2)
#define PPAD_ (DP_*HP_*WP_)    // 33640
#define HPWP_ (HP_*WP_)
#define KTOT 1728              // 64*27 == 8*27*8

#define PREP_W0H (704*KTOT)    // fp16 w_off (648 real, pad 704)
#define PREP_W1H (64*KTOT)     // fp16 w1 in (g,k,cl) dense order
#define PREP_W2H (64*KTOT)     // fp16 w2 in (ci,tap) dense order

// ---------------- scratch (no allocation allowed) ----------------
__device__ float  g_xpad[N_*C_*PPAD_];     // padded input
__device__ float  g_y2pad[N_*C_*PPAD_];    // padded bn1+relu output
__device__ float  g_off[N_*CO_OFF*P_];     // offset tensor (130 MB)
__device__ float4 g_xt[N_*G_*P_*2];        // x transposed [n][g][p][8ch]
__device__ __half g_valsh[(size_t)N_*KTOT*P_]; // sampled values fp16 (173 MB)
__device__ float  g_y1[N_*C_*P_];          // deform conv output
__device__ float  g_y3[N_*C_*P_];          // conv2 output
__device__ float  g_stats[4*C_];           // mean1, istd1, mean2, istd2
__device__ __half g_woffh[PREP_W0H];       // fp16 w_off [cog 704][k 1728]
__device__ __half g_w1h[PREP_W1H];         // fp16 w1 [o][1728]
__device__ __half g_w2h[PREP_W2H];         // fp16 w2 [o][1728]
__device__ __half g_xc[(size_t)N_*KTOT*P_]; // im2col fp16 [n][k][p] (173 MB, reused)

// ---------------- helpers ----------------
__device__ __forceinline__ void mma_fp16(float c[4], const uint32_t a[4],
                                         uint32_t b0, uint32_t b1) {
    asm volatile(
        "mma.sync.aligned.m16n8k16.row.col.f32.f16.f16.f32 "
        "{%0,%1,%2,%3}, {%4,%5,%6,%7}, {%8,%9}, {%0,%1,%2,%3};"
        : "+f"(c[0]), "+f"(c[1]), "+f"(c[2]), "+f"(c[3])
        : "r"(a[0]), "r"(a[1]), "r"(a[2]), "r"(a[3]), "r"(b0), "r"(b1));
}

// ---------------- kernel P: weight prep (all fp16, dense k layouts) ----------------
__global__ void prep_kernel(const float* __restrict__ w_off,
                            const float* __restrict__ w1,
                            const float* __restrict__ w2) {
    int idx = blockIdx.x * 256 + threadIdx.x;
    if (idx < PREP_W0H) {
        int k = idx % KTOT, cog = idx / KTOT;
        float v = (cog < CO_OFF) ? w_off[(size_t)cog * KTOT + k] : 0.f;
        g_woffh[idx] = __float2half_rn(v);
    } else if (idx < PREP_W0H + PREP_W1H) {
        int r = idx - PREP_W0H;
        int kd = r % KTOT, o = r / KTOT;
        int cl = kd & 7, gk = kd >> 3;
        int g = gk / 27, k = gk - g * 27;
        g_w1h[r] = __float2half_rn(w1[(o * C_ + g * 8 + cl) * K_ + k]);
    } else if (idx < PREP_W0H + PREP_W1H + PREP_W2H) {
        int r = idx - PREP_W0H - PREP_W1H;
        g_w2h[r] = __float2half_rn(w2[r]);   // w2 is [O][C][27] = [o][kd] already
    }
}

// ---------------- kernel T: transpose x -> [n][g][p][8ch] ----------------
__global__ void transpose_kernel(const float* __restrict__ x) {
    int idx = blockIdx.x * 256 + threadIdx.x;
    if (idx >= N_*G_*P_) return;
    int p = idx % P_;
    int g = (idx / P_) % G_;
    int n = idx / (P_ * G_);
    const float* xs = x + ((size_t)(n * C_ + g * 8)) * P_ + p;
    float4 a, b;
    a.x = xs[0];            a.y = xs[(size_t)P_];
    a.z = xs[2*(size_t)P_]; a.w = xs[3*(size_t)P_];
    b.x = xs[4*(size_t)P_]; b.y = xs[5*(size_t)P_];
    b.z = xs[6*(size_t)P_]; b.w = xs[7*(size_t)P_];
    g_xt[(size_t)idx * 2]     = a;
    g_xt[(size_t)idx * 2 + 1] = b;
}

// ---------------- kernel 0: build padded x ----------------
__global__ void padinit_kernel(const float* __restrict__ x) {
    int idx = blockIdx.x * 256 + threadIdx.x;
    if (idx >= N_*C_*PPAD_) return;
    int wp = idx % WP_;
    int hp = (idx / WP_) % HP_;
    int dp = (idx / (WP_*HP_)) % DP_;
    int nc = idx / PPAD_;
    bool interior = (dp >= 1 && dp <= D_ && hp >= 1 && hp <= H_ && wp >= 1 && wp <= W_);
    float v = 0.f;
    if (interior)
        v = x[nc * P_ + (dp-1) * (H_*W_) + (hp-1) * W_ + (wp-1)];
    g_xpad[idx] = v;
    if (!interior) g_y2pad[idx] = 0.f;
}

// ---------------- kernel I: im2col fp16  g_xc[n][k][p]  (src: xpad or y2pad) -------
__global__ void im2col_kernel(int use_y2) {
    int idx = blockIdx.x * 256 + threadIdx.x;
    if (idx >= N_ * KTOT * (P_ / 8)) return;
    int p8 = idx % (P_ / 8);
    int k  = (idx / (P_ / 8)) % KTOT;
    int n  = idx / ((P_ / 8) * KTOT);
    int ci = k / 27, tap = k - ci * 27;
    int kd = tap / 9, kh = (tap / 3) % 3, kw = tap % 3;
    int w8 = (p8 % 7) * 8;
    int h  = (p8 / 7) % H_;
    int d  = p8 / 392;
    const float* base = use_y2 ? g_y2pad : g_xpad;
    const float* src = base + (size_t)(n * C_ + ci) * PPAD_
                       + (d + kd) * HPWP_ + (h + kh) * WP_ + (w8 + kw);
    __half out[8];
#pragma unroll
    for (int j = 0; j < 8; j++) out[j] = __float2half_rn(src[j]);
    *(uint4*)(g_xc + ((size_t)(n * KTOT + k)) * P_ + p8 * 8) = *(const uint4*)out;
}

// ---------------- generic fp16 m16n8k16 dense GEMM ----------------
// out[n][co_tot][P] = A[co][KTOT] x Bm[n][KTOT][P].  BM=64 x BN=112, 128 thr.
// grid: (448 = n*224 pos-tiles, ceil(co_tot/64))
__global__ __launch_bounds__(128) void gemm_fp16_kernel(
    const __half* __restrict__ A, const __half* __restrict__ Bm,
    float* __restrict__ outb, const float* __restrict__ bias, int co_tot) {
    __shared__ uint32_t Wsu[64*36];
    __shared__ uint32_t Bsu[32*120];

    int bx = blockIdx.x;
    int pt = bx % 224;
    int n  = bx / 224;
    int pbase = pt * 112;
    int cot = blockIdx.y;

    int tid  = threadIdx.x;
    int lane = tid & 31, warp = tid >> 5;
    int gid  = lane >> 2, tg = lane & 3;
    int mw   = warp >> 1, nw = warp & 1;

    float c[2][7][4];
#pragma unroll
    for (int mt = 0; mt < 2; mt++)
#pragma unroll
        for (int nt = 0; nt < 7; nt++)
#pragma unroll
            for (int i = 0; i < 4; i++) c[mt][nt][i] = 0.f;

    for (int kc = 0; kc < 27; kc++) {
        int k0 = kc * 64;
        __syncthreads();
#pragma unroll
        for (int i = tid; i < 512; i += 128) {
            int co = i >> 3, f = i & 7;
            uint4 v = *(const uint4*)(A + ((size_t)(cot * 64 + co)) * KTOT + k0 + f * 8);
            *(uint4*)&Wsu[co * 36 + f * 4] = v;
        }
#pragma unroll
        for (int i = tid; i < 448; i += 128) {
            int kp = i / 14, pg = i - kp * 14;
            int pos0 = pg * 8;
            const __half* r0 = Bm + ((size_t)(n * KTOT + k0 + 2 * kp)) * P_ + pbase + pos0;
            uint4 a = *(const uint4*)r0;
            uint4 b = *(const uint4*)(r0 + P_);
            uint32_t o0 = __byte_perm(a.x, b.x, 0x5410), o1 = __byte_perm(a.x, b.x, 0x7632);
            uint32_t o2 = __byte_perm(a.y, b.y, 0x5410), o3 = __byte_perm(a.y, b.y, 0x7632);
            uint32_t o4 = __byte_perm(a.z, b.z, 0x5410), o5 = __byte_perm(a.z, b.z, 0x7632);
            uint32_t o6 = __byte_perm(a.w, b.w, 0x5410), o7 = __byte_perm(a.w, b.w, 0x7632);
            int base = kp * 120 + pos0;
            uint4 u0; u0.x = o0; u0.y = o1; u0.z = o2; u0.w = o3;
            uint4 u1; u1.x = o4; u1.y = o5; u1.z = o6; u1.w = o7;
            *(uint4*)&Bsu[base]     = u0;
            *(uint4*)&Bsu[base + 4] = u1;
        }
        __syncthreads();

#pragma unroll
        for (int ks = 0; ks < 4; ks++) {
            uint32_t a[2][4];
#pragma unroll
            for (int mt = 0; mt < 2; mt++) {
                int r = mw * 32 + mt * 16 + gid;
                a[mt][0] = Wsu[r * 36 + ks * 8 + tg];
                a[mt][1] = Wsu[(r + 8) * 36 + ks * 8 + tg];
                a[mt][2] = Wsu[r * 36 + ks * 8 + tg + 4];
                a[mt][3] = Wsu[(r + 8) * 36 + ks * 8 + tg + 4];
            }
#pragma unroll
            for (int nt = 0; nt < 7; nt++) {
                int col = nw * 56 + nt * 8 + gid;
                uint32_t b0 = Bsu[(ks * 8 + tg) * 120 + col];
                uint32_t b1 = Bsu[(ks * 8 + tg + 4) * 120 + col];
                mma_fp16(c[0][nt], a[0], b0, b1);
                mma_fp16(c[1][nt], a[1], b0, b1);
            }
        }
    }

#pragma unroll
    for (int mt = 0; mt < 2; mt++) {
#pragma unroll
        for (int half = 0; half < 2; half++) {
            int co = cot * 64 + mw * 32 + mt * 16 + gid + half * 8;
            if (co < co_tot) {
                float bo = bias ? bias[co] : 0.f;
                float* outp = outb + ((size_t)(n * co_tot + co)) * P_ + pbase;
#pragma unroll
                for (int nt = 0; nt < 7; nt++) {
                    int w0 = nw * 56 + nt * 8 + tg * 2;
                    float2 st;
                    st.x = c[mt][nt][half * 2 + 0] + bo;
                    st.y = c[mt][nt][half * 2 + 1] + bo;
                    *(float2*)&outp[w0] = st;
                }
            }
        }
    }
}

// ---------------- kernel 2a: deform gather (float4 in, fp16 out) ----
__global__ __launch_bounds__(256) void deform_gather_kernel() {
    int bx = blockIdx.x;
    int pc = bx % 98;
    int ngk = bx / 98;
    int k = ngk % K_;
    int g = (ngk / K_) % G_;
    int n = ngk / (K_ * G_);
    int p = pc * 256 + threadIdx.x;

    int w = p % W_;
    int h = (p / W_) % H_;
    int d = p / (W_ * H_);

    int kd = k / 9, kh = (k / 3) % 3, kw = k % 3;
    size_t obase = ((size_t)(n * CO_OFF + (g*K_ + k) * 3)) * P_ + p;
    float od = __ldg(&g_off[obase]);
    float oh = __ldg(&g_off[obase + P_]);
    float ow = __ldg(&g_off[obase + 2*(size_t)P_]);

    float pd = (float)(d + kd - 1) + od;
    float ph = (float)(h + kh - 1) + oh;
    float pw = (float)(w + kw - 1) + ow;
    float d0f = floorf(pd), h0f = floorf(ph), w0f = floorf(pw);
    float fd = pd - d0f, fh = ph - h0f, fw = pw - w0f;
    int d0 = (int)d0f, h0 = (int)h0f, w0 = (int)w0f;

    const float4* xg = (const float4*)g_xt + ((size_t)(n * G_ + g)) * P_ * 2;

    float s0=0.f,s1=0.f,s2=0.f,s3=0.f,s4=0.f,s5=0.f,s6=0.f,s7=0.f;
#pragma unroll
    for (int c8 = 0; c8 < 8; c8++) {
        int cd = c8 >> 2, ch = (c8 >> 1) & 1, cw = c8 & 1;
        int id = d0 + cd, ih = h0 + ch, iw = w0 + cw;
        float wt = (cd ? fd : 1.f - fd) * (ch ? fh : 1.f - fh) * (cw ? fw : 1.f - fw);
        bool valid = (id >= 0 && id < D_ && ih >= 0 && ih < H_ && iw >= 0 && iw < W_);
        int idc = min(max(id, 0), D_-1);
        int ihc = min(max(ih, 0), H_-1);
        int iwc = min(max(iw, 0), W_-1);
        int lin = (idc * H_ + ihc) * W_ + iwc;
        wt = valid ? wt : 0.f;
        float4 va = __ldg(&xg[(size_t)lin * 2]);
        float4 vb = __ldg(&xg[(size_t)lin * 2 + 1]);
        s0 += va.x * wt; s1 += va.y * wt; s2 += va.z * wt; s3 += va.w * wt;
        s4 += vb.x * wt; s5 += vb.y * wt; s6 += vb.z * wt; s7 += vb.w * wt;
    }

    // vals fp16, k_dense = (g*27+k)*8 + cl
    __half* vout = g_valsh + ((size_t)(n * KTOT + (g * K_ + k) * 8)) * P_ + p;
    vout[0]            = __float2half_rn(s0);
    vout[(size_t)P_]   = __float2half_rn(s1);
    vout[2*(size_t)P_] = __float2half_rn(s2);
    vout[3*(size_t)P_] = __float2half_rn(s3);
    vout[4*(size_t)P_] = __float2half_rn(s4);
    vout[5*(size_t)P_] = __float2half_rn(s5);
    vout[6*(size_t)P_] = __float2half_rn(s6);
    vout[7*(size_t)P_] = __float2half_rn(s7);
}

// ---------------- BN statistics ----------------
__global__ void bnstats_kernel(int which) {
    const float* y = which ? g_y3 : g_y1;
    int c = blockIdx.x;
    int tid = threadIdx.x;
    float s = 0.f, s2 = 0.f;
    for (int n = 0; n < N_; n++) {
        const float* p = y + (n * C_ + c) * P_;
        for (int i = tid; i < P_ / 4; i += 256) {
            float4 v = *(const float4*)&p[i * 4];
            s += v.x + v.y + v.z + v.w;
            s2 += v.x*v.x + v.y*v.y + v.z*v.z + v.w*v.w;
        }
    }
    __shared__ float rs[256], rq[256];
    rs[tid] = s; rq[tid] = s2;
    __syncthreads();
    for (int st = 128; st > 0; st >>= 1) {
        if (tid < st) { rs[tid] += rs[tid+st]; rq[tid] += rq[tid+st]; }
        __syncthreads();
    }
    if (tid == 0) {
        float cnt = (float)(N_ * P_);
        float m = rs[0] / cnt;
        float var = rq[0] / cnt - m * m;
        g_stats[which*128 + c]      = m;
        g_stats[which*128 + 64 + c] = rsqrtf(var + 1e-5f);
    }
}

// ---------------- BN1 apply + relu -> padded buffer ----------------
__global__ void bnrelu_kernel(const float* __restrict__ gamma, const float* __restrict__ beta) {
    int i4 = blockIdx.x * 256 + threadIdx.x;
    if (i4 >= N_*C_*P_/4) return;
    int idx = i4 * 4;
    int c = (idx / P_) % C_;
    float m = g_stats[c], is = g_stats[64 + c];
    float ga = gamma[c], be = beta[c];
    float4 v = *(const float4*)&g_y1[idx];
    v.x = fmaxf((v.x - m) * is * ga + be, 0.f);
    v.y = fmaxf((v.y - m) * is * ga + be, 0.f);
    v.z = fmaxf((v.z - m) * is * ga + be, 0.f);
    v.w = fmaxf((v.w - m) * is * ga + be, 0.f);
    int pp = idx % P_;
    int w = pp % W_, hh = (pp / W_) % H_, dd = pp / (W_*H_);
    int nc = idx / P_;
    float* dst = &g_y2pad[nc * PPAD_ + (dd+1) * HPWP_ + (hh+1) * WP_ + (w+1)];
    dst[0] = v.x; dst[1] = v.y; dst[2] = v.z; dst[3] = v.w;
}

// ---------------- final: bn2 + residual + relu (float4) ----------------
__global__ void final_kernel(const float* __restrict__ x,
                             const float* __restrict__ gamma2,
                             const float* __restrict__ beta2,
                             float* __restrict__ out) {
    int i4 = blockIdx.x * 256 + threadIdx.x;
    if (i4 >= N_*C_*P_/4) return;
    int idx = i4 * 4;
    int c = (idx / P_) % C_;
    float m = g_stats[128 + c], is = g_stats[192 + c];
    float ga = gamma2[c], be = beta2[c];
    float4 v = *(const float4*)&g_y3[idx];
    float4 xr = *(const float4*)&x[idx];
    float4 o;
    o.x = fmaxf((v.x - m) * is * ga + be + xr.x, 0.f);
    o.y = fmaxf((v.y - m) * is * ga + be + xr.y, 0.f);
    o.z = fmaxf((v.z - m) * is * ga + be + xr.z, 0.f);
    o.w = fmaxf((v.w - m) * is * ga + be + xr.w, 0.f);
    *(float4*)&out[idx] = o;
}

// ---------------- launcher ----------------
extern "C" void kernel_launch(void* const* d_in, const int* in_sizes, int n_in,
                              void* d_out, int out_size) {
    const float* x      = (const float*)d_in[0];
    const float* w_off  = (const float*)d_in[1];
    const float* b_off  = (const float*)d_in[2];
    const float* w1     = (const float*)d_in[3];
    const float* gamma1 = (const float*)d_in[4];
    const float* beta1  = (const float*)d_in[5];
    const float* w2     = (const float*)d_in[6];
    const float* b2     = (const float*)d_in[7];
    const float* gamma2 = (const float*)d_in[8];
    const float* beta2  = (const float*)d_in[9];
    float* out = (float*)d_out;

    void *p_woffh, *p_w1h, *p_w2h, *p_xc, *p_valsh, *p_off, *p_y1, *p_y3;
    cudaGetSymbolAddress(&p_woffh, g_woffh);
    cudaGetSymbolAddress(&p_w1h,   g_w1h);
    cudaGetSymbolAddress(&p_w2h,   g_w2h);
    cudaGetSymbolAddress(&p_xc,    g_xc);
    cudaGetSymbolAddress(&p_valsh, g_valsh);
    cudaGetSymbolAddress(&p_off,   g_off);
    cudaGetSymbolAddress(&p_y1,    g_y1);
    cudaGetSymbolAddress(&p_y3,    g_y3);

    int padtot = N_*C_*PPAD_;
    int tot4 = N_*C_*P_/4;
    int preptot = PREP_W0H + PREP_W1H + PREP_W2H;
    int im2tot = N_ * KTOT * (P_ / 8);

    prep_kernel<<<(preptot + 255) / 256, 256>>>(w_off, w1, w2);
    padinit_kernel<<<(padtot + 255) / 256, 256>>>(x);
    transpose_kernel<<<(N_*G_*P_ + 255) / 256, 256>>>(x);
    im2col_kernel<<<(im2tot + 255) / 256, 256>>>(0);
    gemm_fp16_kernel<<<dim3(448, 11), 128>>>((const __half*)p_woffh, (const __half*)p_xc,
                                             (float*)p_off, b_off, CO_OFF);
    deform_gather_kernel<<<N_*G_*K_*98, 256>>>();
    gemm_fp16_kernel<<<dim3(448, 1), 128>>>((const __half*)p_w1h, (const __half*)p_valsh,
                                            (float*)p_y1, (const float*)nullptr, C_);
    bnstats_kernel<<<64, 256>>>(0);
    bnrelu_kernel<<<(tot4 + 255) / 256, 256>>>(gamma1, beta1);
    im2col_kernel<<<(im2tot + 255) / 256, 256>>>(1);
    gemm_fp16_kernel<<<dim3(448, 1), 128>>>((const __half*)p_w2h, (const __half*)p_xc,
                                            (float*)p_y3, b2, C_);
    bnstats_kernel<<<64, 256>>>(1);
    final_kernel<<<(tot4 + 255) / 256, 256>>>(x, gamma2, beta2, out);
}

// round 15
// speedup vs baseline: 1.4423x; 1.0167x over previous
#include <cuda_runtime.h>
#include <cuda_fp16.h>
#include <cstdint>

#define N_ 2
#define C_ 64
#define D_ 8
#define H_ 56
#define W_ 56
#define G_ 8
#define K_ 27
#define CO_OFF 648
#define P_ (D_*H_*W_)          // 25088 = 112 * 224
#define DP_ (D_+2)
#define HP_ (H_+2)
#define WP_ (W_+2)
#define PPAD_ (DP_*HP_*WP_)    // 33640
#define HPWP_ (HP_*WP_)
#define KTOT 1728              // 64*27 == 8*27*8

#define PREP_W0H (704*KTOT)    // fp16 w_off (648 real, pad 704)
#define PREP_W1H (64*KTOT)
#define PREP_W2H (64*KTOT)

// ---------------- scratch (no allocation allowed) ----------------
__device__ float  g_xpad[N_*C_*PPAD_];     // padded input
__device__ float  g_y2pad[N_*C_*PPAD_];    // padded bn1+relu output
__device__ float  g_off[N_*CO_OFF*P_];     // offset tensor (130 MB)
__device__ float4 g_xt[N_*G_*P_*2];        // x transposed [n][g][p][8ch]
__device__ __half g_valsh[(size_t)N_*KTOT*P_]; // sampled values fp16 (173 MB)
__device__ float  g_y1[N_*C_*P_];          // deform conv output
__device__ float  g_y3[N_*C_*P_];          // conv2 output
__device__ float  g_stats[4*C_];           // mean1, istd1, mean2, istd2
__device__ __half g_woffh[PREP_W0H];       // fp16 w_off [cog 704][k 1728]
__device__ __half g_w1h[PREP_W1H];         // fp16 w1 [o][1728]
__device__ __half g_w2h[PREP_W2H];         // fp16 w2 [o][1728]
__device__ __half g_xc[(size_t)N_*KTOT*P_]; // im2col fp16 [n][k][p] (reused)

// ---------------- helpers ----------------
__device__ __forceinline__ void mma_fp16(float c[4], const uint32_t a[4],
                                         uint32_t b0, uint32_t b1) {
    asm volatile(
        "mma.sync.aligned.m16n8k16.row.col.f32.f16.f16.f32 "
        "{%0,%1,%2,%3}, {%4,%5,%6,%7}, {%8,%9}, {%0,%1,%2,%3};"
        : "+f"(c[0]), "+f"(c[1]), "+f"(c[2]), "+f"(c[3])
        : "r"(a[0]), "r"(a[1]), "r"(a[2]), "r"(a[3]), "r"(b0), "r"(b1));
}

// ---------------- kernel P: weight prep (all fp16, dense k layouts) ----------------
__global__ void prep_kernel(const float* __restrict__ w_off,
                            const float* __restrict__ w1,
                            const float* __restrict__ w2) {
    int idx = blockIdx.x * 256 + threadIdx.x;
    if (idx < PREP_W0H) {
        int k = idx % KTOT, cog = idx / KTOT;
        float v = (cog < CO_OFF) ? w_off[(size_t)cog * KTOT + k] : 0.f;
        g_woffh[idx] = __float2half_rn(v);
    } else if (idx < PREP_W0H + PREP_W1H) {
        int r = idx - PREP_W0H;
        int kd = r % KTOT, o = r / KTOT;
        int cl = kd & 7, gk = kd >> 3;
        int g = gk / 27, k = gk - g * 27;
        g_w1h[r] = __float2half_rn(w1[(o * C_ + g * 8 + cl) * K_ + k]);
    } else if (idx < PREP_W0H + PREP_W1H + PREP_W2H) {
        int r = idx - PREP_W0H - PREP_W1H;
        g_w2h[r] = __float2half_rn(w2[r]);
    }
}

// ---------------- kernel T: transpose x -> [n][g][p][8ch] ----------------
__global__ void transpose_kernel(const float* __restrict__ x) {
    int idx = blockIdx.x * 256 + threadIdx.x;
    if (idx >= N_*G_*P_) return;
    int p = idx % P_;
    int g = (idx / P_) % G_;
    int n = idx / (P_ * G_);
    const float* xs = x + ((size_t)(n * C_ + g * 8)) * P_ + p;
    float4 a, b;
    a.x = xs[0];            a.y = xs[(size_t)P_];
    a.z = xs[2*(size_t)P_]; a.w = xs[3*(size_t)P_];
    b.x = xs[4*(size_t)P_]; b.y = xs[5*(size_t)P_];
    b.z = xs[6*(size_t)P_]; b.w = xs[7*(size_t)P_];
    g_xt[(size_t)idx * 2]     = a;
    g_xt[(size_t)idx * 2 + 1] = b;
}

// ---------------- kernel 0: build padded x ----------------
__global__ void padinit_kernel(const float* __restrict__ x) {
    int idx = blockIdx.x * 256 + threadIdx.x;
    if (idx >= N_*C_*PPAD_) return;
    int wp = idx % WP_;
    int hp = (idx / WP_) % HP_;
    int dp = (idx / (WP_*HP_)) % DP_;
    int nc = idx / PPAD_;
    bool interior = (dp >= 1 && dp <= D_ && hp >= 1 && hp <= H_ && wp >= 1 && wp <= W_);
    float v = 0.f;
    if (interior)
        v = x[nc * P_ + (dp-1) * (H_*W_) + (hp-1) * W_ + (wp-1)];
    g_xpad[idx] = v;
    if (!interior) g_y2pad[idx] = 0.f;
}

// ---------------- kernel I: im2col fp16  g_xc[n][k][p] ----------------
__global__ void im2col_kernel(int use_y2) {
    int idx = blockIdx.x * 256 + threadIdx.x;
    if (idx >= N_ * KTOT * (P_ / 8)) return;
    int p8 = idx % (P_ / 8);
    int k  = (idx / (P_ / 8)) % KTOT;
    int n  = idx / ((P_ / 8) * KTOT);
    int ci = k / 27, tap = k - ci * 27;
    int kd = tap / 9, kh = (tap / 3) % 3, kw = tap % 3;
    int w8 = (p8 % 7) * 8;
    int h  = (p8 / 7) % H_;
    int d  = p8 / 392;
    const float* base = use_y2 ? g_y2pad : g_xpad;
    const float* src = base + (size_t)(n * C_ + ci) * PPAD_
                       + (d + kd) * HPWP_ + (h + kh) * WP_ + (w8 + kw);
    __half out[8];
#pragma unroll
    for (int j = 0; j < 8; j++) out[j] = __float2half_rn(src[j]);
    *(uint4*)(g_xc + ((size_t)(n * KTOT + k)) * P_ + p8 * 8) = *(const uint4*)out;
}

// ---------------- generic fp16 m16n8k16 dense GEMM, deep-M warps ----------------
// out[n][co_tot][P] = A[co][KTOT] x Bm[n][KTOT][P].
// BM=64, BN=224. 128 thr: 4 warps, each warp M=64 (mt=4) x N=56 (nt=7).
// grid: (224 = n*112 pos-tiles, ceil(co_tot/64))
__global__ __launch_bounds__(128) void gemm_fp16_kernel(
    const __half* __restrict__ A, const __half* __restrict__ Bm,
    float* __restrict__ outb, const float* __restrict__ bias, int co_tot) {
    __shared__ uint32_t Wsu[64*36];       // fp16-pair [co][36]
    __shared__ uint32_t Bsu[2][32*120];   // two 112-pos halves, k-pair interleaved

    int bx = blockIdx.x;
    int pt = bx % 112;
    int n  = bx / 112;
    int pbase = pt * 224;
    int cot = blockIdx.y;

    int tid  = threadIdx.x;
    int lane = tid & 31, warp = tid >> 5;
    int gid  = lane >> 2, tg = lane & 3;
    int nw   = warp;                 // 0..3 N-slices of 56
    int hb   = nw >> 1, nsub = nw & 1;

    float c[4][7][4];
#pragma unroll
    for (int mt = 0; mt < 4; mt++)
#pragma unroll
        for (int nt = 0; nt < 7; nt++)
#pragma unroll
            for (int i = 0; i < 4; i++) c[mt][nt][i] = 0.f;

    for (int kc = 0; kc < 27; kc++) {
        int k0 = kc * 64;
        __syncthreads();
        // stage A: 512 uint4, 4 per thread
#pragma unroll
        for (int i = tid; i < 512; i += 128) {
            int co = i >> 3, f = i & 7;
            uint4 v = *(const uint4*)(A + ((size_t)(cot * 64 + co)) * KTOT + k0 + f * 8);
            *(uint4*)&Wsu[co * 36 + f * 4] = v;
        }
        // stage B: 896 items = 2 halves x 32 kpairs x 14 pos-octets
#pragma unroll
        for (int i = tid; i < 896; i += 128) {
            int hb2 = i / 448;
            int r   = i - hb2 * 448;
            int kp  = r / 14, pg = r - kp * 14;
            int pos0 = pg * 8;
            const __half* r0 = Bm + ((size_t)(n * KTOT + k0 + 2 * kp)) * P_
                               + pbase + hb2 * 112 + pos0;
            uint4 a = *(const uint4*)r0;
            uint4 b = *(const uint4*)(r0 + P_);
            uint32_t o0 = __byte_perm(a.x, b.x, 0x5410), o1 = __byte_perm(a.x, b.x, 0x7632);
            uint32_t o2 = __byte_perm(a.y, b.y, 0x5410), o3 = __byte_perm(a.y, b.y, 0x7632);
            uint32_t o4 = __byte_perm(a.z, b.z, 0x5410), o5 = __byte_perm(a.z, b.z, 0x7632);
            uint32_t o6 = __byte_perm(a.w, b.w, 0x5410), o7 = __byte_perm(a.w, b.w, 0x7632);
            int base = kp * 120 + pos0;
            uint4 u0; u0.x = o0; u0.y = o1; u0.z = o2; u0.w = o3;
            uint4 u1; u1.x = o4; u1.y = o5; u1.z = o6; u1.w = o7;
            *(uint4*)&Bsu[hb2][base]     = u0;
            *(uint4*)&Bsu[hb2][base + 4] = u1;
        }
        __syncthreads();

#pragma unroll
        for (int ks = 0; ks < 4; ks++) {
            uint32_t a[4][4];
#pragma unroll
            for (int mt = 0; mt < 4; mt++) {
                int r = mt * 16 + gid;
                a[mt][0] = Wsu[r * 36 + ks * 8 + tg];
                a[mt][1] = Wsu[(r + 8) * 36 + ks * 8 + tg];
                a[mt][2] = Wsu[r * 36 + ks * 8 + tg + 4];
                a[mt][3] = Wsu[(r + 8) * 36 + ks * 8 + tg + 4];
            }
#pragma unroll
            for (int nt = 0; nt < 7; nt++) {
                int col = nsub * 56 + nt * 8 + gid;
                uint32_t b0 = Bsu[hb][(ks * 8 + tg) * 120 + col];
                uint32_t b1 = Bsu[hb][(ks * 8 + tg + 4) * 120 + col];
#pragma unroll
                for (int mt = 0; mt < 4; mt++)
                    mma_fp16(c[mt][nt], a[mt], b0, b1);
            }
        }
    }

#pragma unroll
    for (int mt = 0; mt < 4; mt++) {
#pragma unroll
        for (int half = 0; half < 2; half++) {
            int co = cot * 64 + mt * 16 + gid + half * 8;
            if (co < co_tot) {
                float bo = bias ? bias[co] : 0.f;
                float* outp = outb + ((size_t)(n * co_tot + co)) * P_ + pbase;
#pragma unroll
                for (int nt = 0; nt < 7; nt++) {
                    int w0 = nw * 56 + nt * 8 + tg * 2;
                    float2 st;
                    st.x = c[mt][nt][half * 2 + 0] + bo;
                    st.y = c[mt][nt][half * 2 + 1] + bo;
                    *(float2*)&outp[w0] = st;
                }
            }
        }
    }
}

// ---------------- kernel 2a: deform gather (float4 in, fp16 out) ----
__global__ __launch_bounds__(256) void deform_gather_kernel() {
    int bx = blockIdx.x;
    int pc = bx % 98;
    int ngk = bx / 98;
    int k = ngk % K_;
    int g = (ngk / K_) % G_;
    int n = ngk / (K_ * G_);
    int p = pc * 256 + threadIdx.x;

    int w = p % W_;
    int h = (p / W_) % H_;
    int d = p / (W_ * H_);

    int kd = k / 9, kh = (k / 3) % 3, kw = k % 3;
    size_t obase = ((size_t)(n * CO_OFF + (g*K_ + k) * 3)) * P_ + p;
    float od = __ldg(&g_off[obase]);
    float oh = __ldg(&g_off[obase + P_]);
    float ow = __ldg(&g_off[obase + 2*(size_t)P_]);

    float pd = (float)(d + kd - 1) + od;
    float ph = (float)(h + kh - 1) + oh;
    float pw = (float)(w + kw - 1) + ow;
    float d0f = floorf(pd), h0f = floorf(ph), w0f = floorf(pw);
    float fd = pd - d0f, fh = ph - h0f, fw = pw - w0f;
    int d0 = (int)d0f, h0 = (int)h0f, w0 = (int)w0f;

    const float4* xg = (const float4*)g_xt + ((size_t)(n * G_ + g)) * P_ * 2;

    float s0=0.f,s1=0.f,s2=0.f,s3=0.f,s4=0.f,s5=0.f,s6=0.f,s7=0.f;
#pragma unroll
    for (int c8 = 0; c8 < 8; c8++) {
        int cd = c8 >> 2, ch = (c8 >> 1) & 1, cw = c8 & 1;
        int id = d0 + cd, ih = h0 + ch, iw = w0 + cw;
        float wt = (cd ? fd : 1.f - fd) * (ch ? fh : 1.f - fh) * (cw ? fw : 1.f - fw);
        bool valid = (id >= 0 && id < D_ && ih >= 0 && ih < H_ && iw >= 0 && iw < W_);
        int idc = min(max(id, 0), D_-1);
        int ihc = min(max(ih, 0), H_-1);
        int iwc = min(max(iw, 0), W_-1);
        int lin = (idc * H_ + ihc) * W_ + iwc;
        wt = valid ? wt : 0.f;
        float4 va = __ldg(&xg[(size_t)lin * 2]);
        float4 vb = __ldg(&xg[(size_t)lin * 2 + 1]);
        s0 += va.x * wt; s1 += va.y * wt; s2 += va.z * wt; s3 += va.w * wt;
        s4 += vb.x * wt; s5 += vb.y * wt; s6 += vb.z * wt; s7 += vb.w * wt;
    }

    __half* vout = g_valsh + ((size_t)(n * KTOT + (g * K_ + k) * 8)) * P_ + p;
    vout[0]            = __float2half_rn(s0);
    vout[(size_t)P_]   = __float2half_rn(s1);
    vout[2*(size_t)P_] = __float2half_rn(s2);
    vout[3*(size_t)P_] = __float2half_rn(s3);
    vout[4*(size_t)P_] = __float2half_rn(s4);
    vout[5*(size_t)P_] = __float2half_rn(s5);
    vout[6*(size_t)P_] = __float2half_rn(s6);
    vout[7*(size_t)P_] = __float2half_rn(s7);
}

// ---------------- BN statistics ----------------
__global__ void bnstats_kernel(int which) {
    const float* y = which ? g_y3 : g_y1;
    int c = blockIdx.x;
    int tid = threadIdx.x;
    float s = 0.f, s2 = 0.f;
    for (int n = 0; n < N_; n++) {
        const float* p = y + (n * C_ + c) * P_;
        for (int i = tid; i < P_ / 4; i += 256) {
            float4 v = *(const float4*)&p[i * 4];
            s += v.x + v.y + v.z + v.w;
            s2 += v.x*v.x + v.y*v.y + v.z*v.z + v.w*v.w;
        }
    }
    __shared__ float rs[256], rq[256];
    rs[tid] = s; rq[tid] = s2;
    __syncthreads();
    for (int st = 128; st > 0; st >>= 1) {
        if (tid < st) { rs[tid] += rs[tid+st]; rq[tid] += rq[tid+st]; }
        __syncthreads();
    }
    if (tid == 0) {
        float cnt = (float)(N_ * P_);
        float m = rs[0] / cnt;
        float var = rq[0] / cnt - m * m;
        g_stats[which*128 + c]      = m;
        g_stats[which*128 + 64 + c] = rsqrtf(var + 1e-5f);
    }
}

// ---------------- BN1 apply + relu -> padded buffer ----------------
__global__ void bnrelu_kernel(const float* __restrict__ gamma, const float* __restrict__ beta) {
    int i4 = blockIdx.x * 256 + threadIdx.x;
    if (i4 >= N_*C_*P_/4) return;
    int idx = i4 * 4;
    int c = (idx / P_) % C_;
    float m = g_stats[c], is = g_stats[64 + c];
    float ga = gamma[c], be = beta[c];
    float4 v = *(const float4*)&g_y1[idx];
    v.x = fmaxf((v.x - m) * is * ga + be, 0.f);
    v.y = fmaxf((v.y - m) * is * ga + be, 0.f);
    v.z = fmaxf((v.z - m) * is * ga + be, 0.f);
    v.w = fmaxf((v.w - m) * is * ga + be, 0.f);
    int pp = idx % P_;
    int w = pp % W_, hh = (pp / W_) % H_, dd = pp / (W_*H_);
    int nc = idx / P_;
    float* dst = &g_y2pad[nc * PPAD_ + (dd+1) * HPWP_ + (hh+1) * WP_ + (w+1)];
    dst[0] = v.x; dst[1] = v.y; dst[2] = v.z; dst[3] = v.w;
}

// ---------------- final: bn2 + residual + relu (float4) ----------------
__global__ void final_kernel(const float* __restrict__ x,
                             const float* __restrict__ gamma2,
                             const float* __restrict__ beta2,
                             float* __restrict__ out) {
    int i4 = blockIdx.x * 256 + threadIdx.x;
    if (i4 >= N_*C_*P_/4) return;
    int idx = i4 * 4;
    int c = (idx / P_) % C_;
    float m = g_stats[128 + c], is = g_stats[192 + c];
    float ga = gamma2[c], be = beta2[c];
    float4 v = *(const float4*)&g_y3[idx];
    float4 xr = *(const float4*)&x[idx];
    float4 o;
    o.x = fmaxf((v.x - m) * is * ga + be + xr.x, 0.f);
    o.y = fmaxf((v.y - m) * is * ga + be + xr.y, 0.f);
    o.z = fmaxf((v.z - m) * is * ga + be + xr.z, 0.f);
    o.w = fmaxf((v.w - m) * is * ga + be + xr.w, 0.f);
    *(float4*)&out[idx] = o;
}

// ---------------- launcher ----------------
extern "C" void kernel_launch(void* const* d_in, const int* in_sizes, int n_in,
                              void* d_out, int out_size) {
    const float* x      = (const float*)d_in[0];
    const float* w_off  = (const float*)d_in[1];
    const float* b_off  = (const float*)d_in[2];
    const float* w1     = (const float*)d_in[3];
    const float* gamma1 = (const float*)d_in[4];
    const float* beta1  = (const float*)d_in[5];
    const float* w2     = (const float*)d_in[6];
    const float* b2     = (const float*)d_in[7];
    const float* gamma2 = (const float*)d_in[8];
    const float* beta2  = (const float*)d_in[9];
    float* out = (float*)d_out;

    void *p_woffh, *p_w1h, *p_w2h, *p_xc, *p_valsh, *p_off, *p_y1, *p_y3;
    cudaGetSymbolAddress(&p_woffh, g_woffh);
    cudaGetSymbolAddress(&p_w1h,   g_w1h);
    cudaGetSymbolAddress(&p_w2h,   g_w2h);
    cudaGetSymbolAddress(&p_xc,    g_xc);
    cudaGetSymbolAddress(&p_valsh, g_valsh);
    cudaGetSymbolAddress(&p_off,   g_off);
    cudaGetSymbolAddress(&p_y1,    g_y1);
    cudaGetSymbolAddress(&p_y3,    g_y3);

    int padtot = N_*C_*PPAD_;
    int tot4 = N_*C_*P_/4;
    int preptot = PREP_W0H + PREP_W1H + PREP_W2H;
    int im2tot = N_ * KTOT * (P_ / 8);

    prep_kernel<<<(preptot + 255) / 256, 256>>>(w_off, w1, w2);
    padinit_kernel<<<(padtot + 255) / 256, 256>>>(x);
    transpose_kernel<<<(N_*G_*P_ + 255) / 256, 256>>>(x);
    im2col_kernel<<<(im2tot + 255) / 256, 256>>>(0);
    gemm_fp16_kernel<<<dim3(224, 11), 128>>>((const __half*)p_woffh, (const __half*)p_xc,
                                             (float*)p_off, b_off, CO_OFF);
    deform_gather_kernel<<<N_*G_*K_*98, 256>>>();
    gemm_fp16_kernel<<<dim3(224, 1), 128>>>((const __half*)p_w1h, (const __half*)p_valsh,
                                            (float*)p_y1, (const float*)nullptr, C_);
    bnstats_kernel<<<64, 256>>>(0);
    bnrelu_kernel<<<(tot4 + 255) / 256, 256>>>(gamma1, beta1);
    im2col_kernel<<<(im2tot + 255) / 256, 256>>>(1);
    gemm_fp16_kernel<<<dim3(224, 1), 128>>>((const __half*)p_w2h, (const __half*)p_xc,
                                            (float*)p_y3, b2, C_);
    bnstats_kernel<<<64, 256>>>(1);
    final_kernel<<<(tot4 + 255) / 256, 256>>>(x, gamma2, beta2, out);
}

// round 16
// speedup vs baseline: 1.5531x; 1.0768x over previous
#include <cuda_runtime.h>
#include <cuda_fp16.h>
#include <cstdint>

#define N_ 2
#define C_ 64
#define D_ 8
#define H_ 56
#define W_ 56
#define G_ 8
#define K_ 27
#define CO_OFF 648
#define P_ (D_*H_*W_)          // 25088 = 112 * 224
#define DP_ (D_+2)
#define HP_ (H_+2)
#define WP_ (W_+2)
#define PPAD_ (DP_*HP_*WP_)    // 33640
#define HPWP_ (HP_*WP_)
#define KTOT 1728              // 64*27 == 8*27*8

#define PREP_W0H (704*KTOT)    // fp16 w_off (648 real, pad 704)
#define PREP_W1H (64*KTOT)
#define PREP_W2H (64*KTOT)

// ---------------- scratch (no allocation allowed) ----------------
__device__ float  g_xpad[N_*C_*PPAD_];     // padded input
__device__ float  g_y2pad[N_*C_*PPAD_];    // padded bn1+relu output
__device__ float  g_off[N_*CO_OFF*P_];     // offset tensor (130 MB)
__device__ float4 g_xt[N_*G_*P_*2];        // x transposed [n][g][p][8ch]
__device__ __half g_valsh[(size_t)N_*KTOT*P_]; // sampled values fp16 (173 MB)
__device__ float  g_y1[N_*C_*P_];          // deform conv output
__device__ float  g_y3[N_*C_*P_];          // conv2 output
__device__ float  g_stats[4*C_];           // mean1, istd1, mean2, istd2
__device__ __half g_woffh[PREP_W0H];       // fp16 w_off [cog 704][k 1728]
__device__ __half g_w1h[PREP_W1H];         // fp16 w1 [o][1728]
__device__ __half g_w2h[PREP_W2H];         // fp16 w2 [o][1728]
__device__ __half g_xc[(size_t)N_*KTOT*P_]; // im2col fp16 [n][k][p] (reused)

// ---------------- helpers ----------------
__device__ __forceinline__ void mma_fp16(float c[4], const uint32_t a[4],
                                         uint32_t b0, uint32_t b1) {
    asm volatile(
        "mma.sync.aligned.m16n8k16.row.col.f32.f16.f16.f32 "
        "{%0,%1,%2,%3}, {%4,%5,%6,%7}, {%8,%9}, {%0,%1,%2,%3};"
        : "+f"(c[0]), "+f"(c[1]), "+f"(c[2]), "+f"(c[3])
        : "r"(a[0]), "r"(a[1]), "r"(a[2]), "r"(a[3]), "r"(b0), "r"(b1));
}

// ---------------- kernel P: weight prep (all fp16, dense k layouts) ----------------
__global__ void prep_kernel(const float* __restrict__ w_off,
                            const float* __restrict__ w1,
                            const float* __restrict__ w2) {
    int idx = blockIdx.x * 256 + threadIdx.x;
    if (idx < PREP_W0H) {
        int k = idx % KTOT, cog = idx / KTOT;
        float v = (cog < CO_OFF) ? w_off[(size_t)cog * KTOT + k] : 0.f;
        g_woffh[idx] = __float2half_rn(v);
    } else if (idx < PREP_W0H + PREP_W1H) {
        int r = idx - PREP_W0H;
        int kd = r % KTOT, o = r / KTOT;
        int cl = kd & 7, gk = kd >> 3;
        int g = gk / 27, k = gk - g * 27;
        g_w1h[r] = __float2half_rn(w1[(o * C_ + g * 8 + cl) * K_ + k]);
    } else if (idx < PREP_W0H + PREP_W1H + PREP_W2H) {
        int r = idx - PREP_W0H - PREP_W1H;
        g_w2h[r] = __float2half_rn(w2[r]);
    }
}

// ---------------- kernel T: transpose x -> [n][g][p][8ch] ----------------
__global__ void transpose_kernel(const float* __restrict__ x) {
    int idx = blockIdx.x * 256 + threadIdx.x;
    if (idx >= N_*G_*P_) return;
    int p = idx % P_;
    int g = (idx / P_) % G_;
    int n = idx / (P_ * G_);
    const float* xs = x + ((size_t)(n * C_ + g * 8)) * P_ + p;
    float4 a, b;
    a.x = xs[0];            a.y = xs[(size_t)P_];
    a.z = xs[2*(size_t)P_]; a.w = xs[3*(size_t)P_];
    b.x = xs[4*(size_t)P_]; b.y = xs[5*(size_t)P_];
    b.z = xs[6*(size_t)P_]; b.w = xs[7*(size_t)P_];
    g_xt[(size_t)idx * 2]     = a;
    g_xt[(size_t)idx * 2 + 1] = b;
}

// ---------------- kernel 0: build padded x ----------------
__global__ void padinit_kernel(const float* __restrict__ x) {
    int idx = blockIdx.x * 256 + threadIdx.x;
    if (idx >= N_*C_*PPAD_) return;
    int wp = idx % WP_;
    int hp = (idx / WP_) % HP_;
    int dp = (idx / (WP_*HP_)) % DP_;
    int nc = idx / PPAD_;
    bool interior = (dp >= 1 && dp <= D_ && hp >= 1 && hp <= H_ && wp >= 1 && wp <= W_);
    float v = 0.f;
    if (interior)
        v = x[nc * P_ + (dp-1) * (H_*W_) + (hp-1) * W_ + (wp-1)];
    g_xpad[idx] = v;
    if (!interior) g_y2pad[idx] = 0.f;
}

// ---------------- kernel I: im2col fp16  g_xc[n][k][p] ----------------
__global__ void im2col_kernel(int use_y2) {
    int idx = blockIdx.x * 256 + threadIdx.x;
    if (idx >= N_ * KTOT * (P_ / 8)) return;
    int p8 = idx % (P_ / 8);
    int k  = (idx / (P_ / 8)) % KTOT;
    int n  = idx / ((P_ / 8) * KTOT);
    int ci = k / 27, tap = k - ci * 27;
    int kd = tap / 9, kh = (tap / 3) % 3, kw = tap % 3;
    int w8 = (p8 % 7) * 8;
    int h  = (p8 / 7) % H_;
    int d  = p8 / 392;
    const float* base = use_y2 ? g_y2pad : g_xpad;
    const float* src = base + (size_t)(n * C_ + ci) * PPAD_
                       + (d + kd) * HPWP_ + (h + kh) * WP_ + (w8 + kw);
    __half out[8];
#pragma unroll
    for (int j = 0; j < 8; j++) out[j] = __float2half_rn(src[j]);
    *(uint4*)(g_xc + ((size_t)(n * KTOT + k)) * P_ + p8 * 8) = *(const uint4*)out;
}

// ---------------- generic fp16 m16n8k16 dense GEMM, deep-M warps ----------------
// out[n][co_tot][P] = A[co][KTOT] x Bm[n][KTOT][P].
// BM=64, BN=224. 128 thr: 4 warps, each warp M=64 (mt=4) x N=56 (nt=7).
// grid: (ceil(co_tot/64), 224)  — co fastest so co-tiles sharing a pos-tile are
// launch-adjacent and share B reads through L2 (B is the DRAM hog).
__global__ __launch_bounds__(128) void gemm_fp16_kernel(
    const __half* __restrict__ A, const __half* __restrict__ Bm,
    float* __restrict__ outb, const float* __restrict__ bias, int co_tot) {
    __shared__ uint32_t Wsu[64*36];       // fp16-pair [co][36]
    __shared__ uint32_t Bsu[2][32*120];   // two 112-pos halves, k-pair interleaved

    int cot = blockIdx.x;
    int bx  = blockIdx.y;
    int pt  = bx % 112;
    int n   = bx / 112;
    int pbase = pt * 224;

    int tid  = threadIdx.x;
    int lane = tid & 31, warp = tid >> 5;
    int gid  = lane >> 2, tg = lane & 3;
    int nw   = warp;                 // 0..3 N-slices of 56
    int hb   = nw >> 1, nsub = nw & 1;

    float c[4][7][4];
#pragma unroll
    for (int mt = 0; mt < 4; mt++)
#pragma unroll
        for (int nt = 0; nt < 7; nt++)
#pragma unroll
            for (int i = 0; i < 4; i++) c[mt][nt][i] = 0.f;

    for (int kc = 0; kc < 27; kc++) {
        int k0 = kc * 64;
        __syncthreads();
        // stage A: 512 uint4, 4 per thread
#pragma unroll
        for (int i = tid; i < 512; i += 128) {
            int co = i >> 3, f = i & 7;
            uint4 v = *(const uint4*)(A + ((size_t)(cot * 64 + co)) * KTOT + k0 + f * 8);
            *(uint4*)&Wsu[co * 36 + f * 4] = v;
        }
        // stage B: 896 items = 2 halves x 32 kpairs x 14 pos-octets
#pragma unroll
        for (int i = tid; i < 896; i += 128) {
            int hb2 = i / 448;
            int r   = i - hb2 * 448;
            int kp  = r / 14, pg = r - kp * 14;
            int pos0 = pg * 8;
            const __half* r0 = Bm + ((size_t)(n * KTOT + k0 + 2 * kp)) * P_
                               + pbase + hb2 * 112 + pos0;
            uint4 a = *(const uint4*)r0;
            uint4 b = *(const uint4*)(r0 + P_);
            uint32_t o0 = __byte_perm(a.x, b.x, 0x5410), o1 = __byte_perm(a.x, b.x, 0x7632);
            uint32_t o2 = __byte_perm(a.y, b.y, 0x5410), o3 = __byte_perm(a.y, b.y, 0x7632);
            uint32_t o4 = __byte_perm(a.z, b.z, 0x5410), o5 = __byte_perm(a.z, b.z, 0x7632);
            uint32_t o6 = __byte_perm(a.w, b.w, 0x5410), o7 = __byte_perm(a.w, b.w, 0x7632);
            int base = kp * 120 + pos0;
            uint4 u0; u0.x = o0; u0.y = o1; u0.z = o2; u0.w = o3;
            uint4 u1; u1.x = o4; u1.y = o5; u1.z = o6; u1.w = o7;
            *(uint4*)&Bsu[hb2][base]     = u0;
            *(uint4*)&Bsu[hb2][base + 4] = u1;
        }
        __syncthreads();

#pragma unroll
        for (int ks = 0; ks < 4; ks++) {
            uint32_t a[4][4];
#pragma unroll
            for (int mt = 0; mt < 4; mt++) {
                int r = mt * 16 + gid;
                a[mt][0] = Wsu[r * 36 + ks * 8 + tg];
                a[mt][1] = Wsu[(r + 8) * 36 + ks * 8 + tg];
                a[mt][2] = Wsu[r * 36 + ks * 8 + tg + 4];
                a[mt][3] = Wsu[(r + 8) * 36 + ks * 8 + tg + 4];
            }
#pragma unroll
            for (int nt = 0; nt < 7; nt++) {
                int col = nsub * 56 + nt * 8 + gid;
                uint32_t b0 = Bsu[hb][(ks * 8 + tg) * 120 + col];
                uint32_t b1 = Bsu[hb][(ks * 8 + tg + 4) * 120 + col];
#pragma unroll
                for (int mt = 0; mt < 4; mt++)
                    mma_fp16(c[mt][nt], a[mt], b0, b1);
            }
        }
    }

#pragma unroll
    for (int mt = 0; mt < 4; mt++) {
#pragma unroll
        for (int half = 0; half < 2; half++) {
            int co = cot * 64 + mt * 16 + gid + half * 8;
            if (co < co_tot) {
                float bo = bias ? bias[co] : 0.f;
                float* outp = outb + ((size_t)(n * co_tot + co)) * P_ + pbase;
#pragma unroll
                for (int nt = 0; nt < 7; nt++) {
                    int w0 = nw * 56 + nt * 8 + tg * 2;
                    float2 st;
                    st.x = c[mt][nt][half * 2 + 0] + bo;
                    st.y = c[mt][nt][half * 2 + 1] + bo;
                    *(float2*)&outp[w0] = st;
                }
            }
        }
    }
}

// ---------------- kernel 2a: deform gather (float4 in, fp16 out) ----
__global__ __launch_bounds__(256) void deform_gather_kernel() {
    int bx = blockIdx.x;
    int pc = bx % 98;
    int ngk = bx / 98;
    int k = ngk % K_;
    int g = (ngk / K_) % G_;
    int n = ngk / (K_ * G_);
    int p = pc * 256 + threadIdx.x;

    int w = p % W_;
    int h = (p / W_) % H_;
    int d = p / (W_ * H_);

    int kd = k / 9, kh = (k / 3) % 3, kw = k % 3;
    size_t obase = ((size_t)(n * CO_OFF + (g*K_ + k) * 3)) * P_ + p;
    float od = __ldg(&g_off[obase]);
    float oh = __ldg(&g_off[obase + P_]);
    float ow = __ldg(&g_off[obase + 2*(size_t)P_]);

    float pd = (float)(d + kd - 1) + od;
    float ph = (float)(h + kh - 1) + oh;
    float pw = (float)(w + kw - 1) + ow;
    float d0f = floorf(pd), h0f = floorf(ph), w0f = floorf(pw);
    float fd = pd - d0f, fh = ph - h0f, fw = pw - w0f;
    int d0 = (int)d0f, h0 = (int)h0f, w0 = (int)w0f;

    const float4* xg = (const float4*)g_xt + ((size_t)(n * G_ + g)) * P_ * 2;

    float s0=0.f,s1=0.f,s2=0.f,s3=0.f,s4=0.f,s5=0.f,s6=0.f,s7=0.f;
#pragma unroll
    for (int c8 = 0; c8 < 8; c8++) {
        int cd = c8 >> 2, ch = (c8 >> 1) & 1, cw = c8 & 1;
        int id = d0 + cd, ih = h0 + ch, iw = w0 + cw;
        float wt = (cd ? fd : 1.f - fd) * (ch ? fh : 1.f - fh) * (cw ? fw : 1.f - fw);
        bool valid = (id >= 0 && id < D_ && ih >= 0 && ih < H_ && iw >= 0 && iw < W_);
        int idc = min(max(id, 0), D_-1);
        int ihc = min(max(ih, 0), H_-1);
        int iwc = min(max(iw, 0), W_-1);
        int lin = (idc * H_ + ihc) * W_ + iwc;
        wt = valid ? wt : 0.f;
        float4 va = __ldg(&xg[(size_t)lin * 2]);
        float4 vb = __ldg(&xg[(size_t)lin * 2 + 1]);
        s0 += va.x * wt; s1 += va.y * wt; s2 += va.z * wt; s3 += va.w * wt;
        s4 += vb.x * wt; s5 += vb.y * wt; s6 += vb.z * wt; s7 += vb.w * wt;
    }

    __half* vout = g_valsh + ((size_t)(n * KTOT + (g * K_ + k) * 8)) * P_ + p;
    vout[0]            = __float2half_rn(s0);
    vout[(size_t)P_]   = __float2half_rn(s1);
    vout[2*(size_t)P_] = __float2half_rn(s2);
    vout[3*(size_t)P_] = __float2half_rn(s3);
    vout[4*(size_t)P_] = __float2half_rn(s4);
    vout[5*(size_t)P_] = __float2half_rn(s5);
    vout[6*(size_t)P_] = __float2half_rn(s6);
    vout[7*(size_t)P_] = __float2half_rn(s7);
}

// ---------------- BN statistics ----------------
__global__ void bnstats_kernel(int which) {
    const float* y = which ? g_y3 : g_y1;
    int c = blockIdx.x;
    int tid = threadIdx.x;
    float s = 0.f, s2 = 0.f;
    for (int n = 0; n < N_; n++) {
        const float* p = y + (n * C_ + c) * P_;
        for (int i = tid; i < P_ / 4; i += 256) {
            float4 v = *(const float4*)&p[i * 4];
            s += v.x + v.y + v.z + v.w;
            s2 += v.x*v.x + v.y*v.y + v.z*v.z + v.w*v.w;
        }
    }
    __shared__ float rs[256], rq[256];
    rs[tid] = s; rq[tid] = s2;
    __syncthreads();
    for (int st = 128; st > 0; st >>= 1) {
        if (tid < st) { rs[tid] += rs[tid+st]; rq[tid] += rq[tid+st]; }
        __syncthreads();
    }
    if (tid == 0) {
        float cnt = (float)(N_ * P_);
        float m = rs[0] / cnt;
        float var = rq[0] / cnt - m * m;
        g_stats[which*128 + c]      = m;
        g_stats[which*128 + 64 + c] = rsqrtf(var + 1e-5f);
    }
}

// ---------------- BN1 apply + relu -> padded buffer ----------------
__global__ void bnrelu_kernel(const float* __restrict__ gamma, const float* __restrict__ beta) {
    int i4 = blockIdx.x * 256 + threadIdx.x;
    if (i4 >= N_*C_*P_/4) return;
    int idx = i4 * 4;
    int c = (idx / P_) % C_;
    float m = g_stats[c], is = g_stats[64 + c];
    float ga = gamma[c], be = beta[c];
    float4 v = *(const float4*)&g_y1[idx];
    v.x = fmaxf((v.x - m) * is * ga + be, 0.f);
    v.y = fmaxf((v.y - m) * is * ga + be, 0.f);
    v.z = fmaxf((v.z - m) * is * ga + be, 0.f);
    v.w = fmaxf((v.w - m) * is * ga + be, 0.f);
    int pp = idx % P_;
    int w = pp % W_, hh = (pp / W_) % H_, dd = pp / (W_*H_);
    int nc = idx / P_;
    float* dst = &g_y2pad[nc * PPAD_ + (dd+1) * HPWP_ + (hh+1) * WP_ + (w+1)];
    dst[0] = v.x; dst[1] = v.y; dst[2] = v.z; dst[3] = v.w;
}

// ---------------- final: bn2 + residual + relu (float4) ----------------
__global__ void final_kernel(const float* __restrict__ x,
                             const float* __restrict__ gamma2,
                             const float* __restrict__ beta2,
                             float* __restrict__ out) {
    int i4 = blockIdx.x * 256 + threadIdx.x;
    if (i4 >= N_*C_*P_/4) return;
    int idx = i4 * 4;
    int c = (idx / P_) % C_;
    float m = g_stats[128 + c], is = g_stats[192 + c];
    float ga = gamma2[c], be = beta2[c];
    float4 v = *(const float4*)&g_y3[idx];
    float4 xr = *(const float4*)&x[idx];
    float4 o;
    o.x = fmaxf((v.x - m) * is * ga + be + xr.x, 0.f);
    o.y = fmaxf((v.y - m) * is * ga + be + xr.y, 0.f);
    o.z = fmaxf((v.z - m) * is * ga + be + xr.z, 0.f);
    o.w = fmaxf((v.w - m) * is * ga + be + xr.w, 0.f);
    *(float4*)&out[idx] = o;
}

// ---------------- launcher ----------------
extern "C" void kernel_launch(void* const* d_in, const int* in_sizes, int n_in,
                              void* d_out, int out_size) {
    const float* x      = (const float*)d_in[0];
    const float* w_off  = (const float*)d_in[1];
    const float* b_off  = (const float*)d_in[2];
    const float* w1     = (const float*)d_in[3];
    const float* gamma1 = (const float*)d_in[4];
    const float* beta1  = (const float*)d_in[5];
    const float* w2     = (const float*)d_in[6];
    const float* b2     = (const float*)d_in[7];
    const float* gamma2 = (const float*)d_in[8];
    const float* beta2  = (const float*)d_in[9];
    float* out = (float*)d_out;

    void *p_woffh, *p_w1h, *p_w2h, *p_xc, *p_valsh, *p_off, *p_y1, *p_y3;
    cudaGetSymbolAddress(&p_woffh, g_woffh);
    cudaGetSymbolAddress(&p_w1h,   g_w1h);
    cudaGetSymbolAddress(&p_w2h,   g_w2h);
    cudaGetSymbolAddress(&p_xc,    g_xc);
    cudaGetSymbolAddress(&p_valsh, g_valsh);
    cudaGetSymbolAddress(&p_off,   g_off);
    cudaGetSymbolAddress(&p_y1,    g_y1);
    cudaGetSymbolAddress(&p_y3,    g_y3);

    int padtot = N_*C_*PPAD_;
    int tot4 = N_*C_*P_/4;
    int preptot = PREP_W0H + PREP_W1H + PREP_W2H;
    int im2tot = N_ * KTOT * (P_ / 8);

    prep_kernel<<<(preptot + 255) / 256, 256>>>(w_off, w1, w2);
    padinit_kernel<<<(padtot + 255) / 256, 256>>>(x);
    transpose_kernel<<<(N_*G_*P_ + 255) / 256, 256>>>(x);
    im2col_kernel<<<(im2tot + 255) / 256, 256>>>(0);
    gemm_fp16_kernel<<<dim3(11, 224), 128>>>((const __half*)p_woffh, (const __half*)p_xc,
                                             (float*)p_off, b_off, CO_OFF);
    deform_gather_kernel<<<N_*G_*K_*98, 256>>>();
    gemm_fp16_kernel<<<dim3(1, 224), 128>>>((const __half*)p_w1h, (const __half*)p_valsh,
                                            (float*)p_y1, (const float*)nullptr, C_);
    bnstats_kernel<<<64, 256>>>(0);
    bnrelu_kernel<<<(tot4 + 255) / 256, 256>>>(gamma1, beta1);
    im2col_kernel<<<(im2tot + 255) / 256, 256>>>(1);
    gemm_fp16_kernel<<<dim3(1, 224), 128>>>((const __half*)p_w2h, (const __half*)p_xc,
                                            (float*)p_y3, b2, C_);
    bnstats_kernel<<<64, 256>>>(1);
    final_kernel<<<(tot4 + 255) / 256, 256>>>(x, gamma2, beta2, out);
}